// round 1
// baseline (speedup 1.0000x reference)
#include <cuda_runtime.h>
#include <cuda_bf16.h>
#include <math.h>

// ---------------- problem constants ----------------
#define VV 32000
#define DD 512
#define DI 1024
#define DS 16
#define DC 4
#define DTR 32
#define LL 4
#define HH 2048
#define BB 2
#define TT 1024
#define BT (BB*TT)   // 2048

// ---------------- scratch (static device memory; no allocs allowed) ----------------
__device__ float g_x   [BT*DD];
__device__ float g_xn  [BT*DD];
__device__ float g_xz  [BT*2*DI];
__device__ float g_u   [BT*DI];
__device__ float g_xdbl[BT*64];
__device__ float g_dt  [BT*DI];
__device__ float g_ym  [BT*DI];
__device__ float g_hh  [BT*HH];

// ---------------- embedding ----------------
__global__ void embed_kernel(const int* __restrict__ idx,
                             const float* __restrict__ tok_emb,
                             const float* __restrict__ pos_emb,
                             float* __restrict__ x)
{
    int tid = blockIdx.x * blockDim.x + threadIdx.x;   // BT*DD total
    int d   = tid & (DD-1);
    int tok = tid >> 9;            // b*T + t
    int t   = tok & (TT-1);
    int id  = idx[tok];
    x[tid] = tok_emb[(size_t)id*DD + d] + pos_emb[(size_t)t*DD + d];
}

// ---------------- layer norm (one block per token, 256 threads, D=512) ----------------
__global__ __launch_bounds__(256) void ln_kernel(const float* __restrict__ x,
                                                 const float* __restrict__ gamma,
                                                 const float* __restrict__ beta,
                                                 float* __restrict__ out)
{
    int tok = blockIdx.x;
    const float* xr = x + (size_t)tok * DD;
    int tid = threadIdx.x;
    float v0 = xr[tid], v1 = xr[tid + 256];

    __shared__ float sm[8];
    __shared__ float mv[2];

    float s = v0 + v1;
    #pragma unroll
    for (int o = 16; o; o >>= 1) s += __shfl_xor_sync(0xffffffffu, s, o);
    int w = tid >> 5, ln = tid & 31;
    if (ln == 0) sm[w] = s;
    __syncthreads();
    if (tid == 0) {
        float tot = 0.f;
        #pragma unroll
        for (int i = 0; i < 8; i++) tot += sm[i];
        mv[0] = tot * (1.f / DD);
    }
    __syncthreads();
    float m  = mv[0];
    float d0 = v0 - m, d1 = v1 - m;
    float sq = d0*d0 + d1*d1;
    #pragma unroll
    for (int o = 16; o; o >>= 1) sq += __shfl_xor_sync(0xffffffffu, sq, o);
    if (ln == 0) sm[w] = sq;
    __syncthreads();
    if (tid == 0) {
        float tot = 0.f;
        #pragma unroll
        for (int i = 0; i < 8; i++) tot += sm[i];
        mv[1] = rsqrtf(tot * (1.f / DD) + 1e-5f);
    }
    __syncthreads();
    float rs = mv[1];
    out[(size_t)tok*DD + tid]       = d0 * rs * gamma[tid]       + beta[tid];
    out[(size_t)tok*DD + tid + 256] = d1 * rs * gamma[tid + 256] + beta[tid + 256];
}

// ---------------- causal depthwise conv (DC=4) + silu ----------------
__global__ void conv_silu_kernel(const float* __restrict__ xz,
                                 const float* __restrict__ w,
                                 const float* __restrict__ cb,
                                 float* __restrict__ u)
{
    int tid = blockIdx.x * blockDim.x + threadIdx.x;   // BT*DI
    int i = tid & (DI-1);
    int t = (tid >> 10) & (TT-1);
    int b = tid >> 20;
    float4 wv = *(const float4*)(w + (size_t)i * 4);
    const float* base = xz + ((size_t)(b*TT) + t) * (2*DI) + i;
    float acc = cb[i];
    acc += wv.w * base[0];
    if (t >= 1) acc += wv.z * base[-(2*DI)];
    if (t >= 2) acc += wv.y * base[-2*(2*DI)];
    if (t >= 3) acc += wv.x * base[-3*(2*DI)];
    float sg = 1.f / (1.f + __expf(-acc));
    u[tid] = acc * sg;
}

// ---------------- selective scan: thread per (b,d,s), 16-lane shfl reduce ----------------
__global__ __launch_bounds__(256) void scan_kernel(const float* __restrict__ dt,
                                                   const float* __restrict__ u,
                                                   const float* __restrict__ xdbl,
                                                   const float* __restrict__ xz,
                                                   const float* __restrict__ A_log,
                                                   const float* __restrict__ D_p,
                                                   float* __restrict__ ym)
{
    int tid = blockIdx.x * blockDim.x + threadIdx.x;   // BB*DI*DS = 32768
    int s = tid & (DS-1);
    int d = (tid >> 4) & (DI-1);
    int b = tid >> 14;

    float Ads = -expf(A_log[(size_t)d*DS + s]);
    float Dv  = D_p[d];
    float h = 0.f;

    const float* dt_p = dt   + (size_t)b*TT*DI + d;
    const float* u_p  = u    + (size_t)b*TT*DI + d;
    const float* bd   = xdbl + (size_t)b*TT*64 + DTR + s;
    const float* cd   = xdbl + (size_t)b*TT*64 + DTR + DS + s;
    const float* zp   = xz   + (size_t)b*TT*(2*DI) + DI + d;
    float*       yp   = ym   + (size_t)b*TT*DI + d;

    for (int t = 0; t < TT; t++) {
        float dtv = dt_p[(size_t)t*DI];
        float uv  = u_p [(size_t)t*DI];
        float Bv  = bd  [(size_t)t*64];
        float Cv  = cd  [(size_t)t*64];
        float dA  = __expf(dtv * Ads);
        h = fmaf(dA, h, dtv * uv * Bv);
        float p = h * Cv;
        p += __shfl_xor_sync(0xffffffffu, p, 1);
        p += __shfl_xor_sync(0xffffffffu, p, 2);
        p += __shfl_xor_sync(0xffffffffu, p, 4);
        p += __shfl_xor_sync(0xffffffffu, p, 8);
        if (s == 0) {
            float zv = zp[(size_t)t*(2*DI)];
            float y  = fmaf(uv, Dv, p);
            y = y * (zv / (1.f + __expf(-zv)));
            yp[(size_t)t*DI] = y;
        }
    }
}

// ---------------- fp32 GEMM (NT): C[m,n] = sum_k A[m,k] * B[n,k], packed f32x2 FMA ----------------
// BIAS: add bias[n]; ACT: 0 none, 1 relu, 2 softplus; RES: add res[m,n] after activation.
#define GBM 128
#define GBN 128
#define GBK 8

__device__ __forceinline__ unsigned long long pack_dup(float a) {
    unsigned long long r;
    asm("mov.b64 %0, {%1, %1};" : "=l"(r) : "f"(a));
    return r;
}

template<int BIAS, int ACT, int RES>
__global__ __launch_bounds__(256) void sgemm_nt(const float* __restrict__ A, int lda,
                                                const float* __restrict__ Bw, int ldb,
                                                const float* __restrict__ bias,
                                                const float* __restrict__ res,
                                                float* __restrict__ C, int ldc,
                                                int M, int N, int K)
{
    __shared__ float As[GBK][GBM];
    __shared__ float Bs[GBK][GBN];

    int tid = threadIdx.x;
    int m0 = blockIdx.y * GBM;
    int n0 = blockIdx.x * GBN;

    int loadRow = tid >> 1;          // 0..127
    int loadK4  = (tid & 1) * 4;     // 0 or 4

    int tx = tid & 15, ty = tid >> 4;
    int row0 = ty * 8, col0 = tx * 8;

    unsigned long long acc[8][4];
    #pragma unroll
    for (int i = 0; i < 8; i++)
        #pragma unroll
        for (int j = 0; j < 4; j++) acc[i][j] = 0ULL;

    for (int k0 = 0; k0 < K; k0 += GBK) {
        float4 av = *(const float4*)(A + (size_t)(m0 + loadRow) * lda + k0 + loadK4);
        float4 bv = make_float4(0.f, 0.f, 0.f, 0.f);
        int nrow = n0 + loadRow;
        if (nrow < N)
            bv = *(const float4*)(Bw + (size_t)nrow * ldb + k0 + loadK4);

        __syncthreads();
        As[loadK4+0][loadRow] = av.x;
        As[loadK4+1][loadRow] = av.y;
        As[loadK4+2][loadRow] = av.z;
        As[loadK4+3][loadRow] = av.w;
        Bs[loadK4+0][loadRow] = bv.x;
        Bs[loadK4+1][loadRow] = bv.y;
        Bs[loadK4+2][loadRow] = bv.z;
        Bs[loadK4+3][loadRow] = bv.w;
        __syncthreads();

        #pragma unroll
        for (int kk = 0; kk < GBK; kk++) {
            float a[8];
            *(float4*)&a[0] = *(const float4*)&As[kk][row0];
            *(float4*)&a[4] = *(const float4*)&As[kk][row0 + 4];
            unsigned long long b2[4];
            const unsigned long long* bp = (const unsigned long long*)&Bs[kk][col0];
            b2[0] = bp[0]; b2[1] = bp[1]; b2[2] = bp[2]; b2[3] = bp[3];
            #pragma unroll
            for (int i = 0; i < 8; i++) {
                unsigned long long aa = pack_dup(a[i]);
                #pragma unroll
                for (int j = 0; j < 4; j++)
                    asm("fma.rn.f32x2 %0, %1, %2, %0;" : "+l"(acc[i][j]) : "l"(aa), "l"(b2[j]));
            }
        }
    }

    #pragma unroll
    for (int i = 0; i < 8; i++) {
        int m = m0 + row0 + i;
        float vr[8];
        #pragma unroll
        for (int j = 0; j < 4; j++)
            asm("mov.b64 {%0, %1}, %2;" : "=f"(vr[2*j]), "=f"(vr[2*j+1]) : "l"(acc[i][j]));
        #pragma unroll
        for (int j = 0; j < 8; j++) {
            int n = n0 + col0 + j;
            if (n < N) {
                float v = vr[j];
                if (BIAS) v += bias[n];
                if (ACT == 1) v = fmaxf(v, 0.f);
                if (ACT == 2) v = (v > 20.f) ? v : log1pf(expf(v));
                if (RES) v += res[(size_t)m * ldc + n];
                C[(size_t)m * ldc + n] = v;
            }
        }
    }
}

// ---------------- launch ----------------
extern "C" void kernel_launch(void* const* d_in, const int* in_sizes, int n_in,
                              void* d_out, int out_size)
{
    const int*   idx     = (const int*)  d_in[0];
    const float* tok_emb = (const float*)d_in[1];
    const float* pos_emb = (const float*)d_in[2];
    const float* ln1_g   = (const float*)d_in[3];
    const float* ln1_b   = (const float*)d_in[4];
    const float* W_in    = (const float*)d_in[5];
    const float* conv_w  = (const float*)d_in[6];
    const float* conv_b  = (const float*)d_in[7];
    const float* W_xp    = (const float*)d_in[8];
    const float* W_dt    = (const float*)d_in[9];
    const float* b_dt    = (const float*)d_in[10];
    const float* A_log   = (const float*)d_in[11];
    const float* D_p     = (const float*)d_in[12];
    const float* W_out   = (const float*)d_in[13];
    const float* ln2_g   = (const float*)d_in[14];
    const float* ln2_b   = (const float*)d_in[15];
    const float* W_f1    = (const float*)d_in[16];
    const float* b_f1    = (const float*)d_in[17];
    const float* W_f2    = (const float*)d_in[18];
    const float* b_f2    = (const float*)d_in[19];
    const float* lm_w    = (const float*)d_in[20];
    const float* lm_b    = (const float*)d_in[21];
    float* logits = (float*)d_out;

    float *x, *xn, *xz, *u, *xdbl, *dt, *ym, *hh;
    cudaGetSymbolAddress((void**)&x,    g_x);
    cudaGetSymbolAddress((void**)&xn,   g_xn);
    cudaGetSymbolAddress((void**)&xz,   g_xz);
    cudaGetSymbolAddress((void**)&u,    g_u);
    cudaGetSymbolAddress((void**)&xdbl, g_xdbl);
    cudaGetSymbolAddress((void**)&dt,   g_dt);
    cudaGetSymbolAddress((void**)&ym,   g_ym);
    cudaGetSymbolAddress((void**)&hh,   g_hh);

    embed_kernel<<<(BT*DD)/256, 256>>>(idx, tok_emb, pos_emb, x);

    for (int l = 0; l < LL; l++) {
        // ln1
        ln_kernel<<<BT, 256>>>(x, ln1_g + l*DD, ln1_b + l*DD, xn);
        // xz = xn @ W_in^T   (2048 x 2048 x 512)
        sgemm_nt<0,0,0><<<dim3(2*DI/GBN, BT/GBM), 256>>>(
            xn, DD, W_in + (size_t)l*2*DI*DD, DD, nullptr, nullptr, xz, 2*DI, BT, 2*DI, DD);
        // depthwise conv + silu -> u
        conv_silu_kernel<<<(BT*DI)/256, 256>>>(xz, conv_w + (size_t)l*DI*DC, conv_b + l*DI, u);
        // x_dbl = u @ W_xp^T   (2048 x 64 x 1024)
        sgemm_nt<0,0,0><<<dim3(1, BT/GBM), 256>>>(
            u, DI, W_xp + (size_t)l*64*DI, DI, nullptr, nullptr, xdbl, 64, BT, 64, DI);
        // dt = softplus(x_dbl[:, :32] @ W_dt^T + b_dt)   (2048 x 1024 x 32), A lda=64
        sgemm_nt<1,2,0><<<dim3(DI/GBN, BT/GBM), 256>>>(
            xdbl, 64, W_dt + (size_t)l*DI*DTR, DTR, b_dt + l*DI, nullptr, dt, DI, BT, DI, DTR);
        // selective scan -> ym (fused +u*D_p and *silu(z))
        scan_kernel<<<(BB*DI*DS)/256, 256>>>(dt, u, xdbl, xz,
                                             A_log + (size_t)l*DI*DS, D_p + l*DI, ym);
        // x += ym @ W_out^T   (2048 x 512 x 1024)
        sgemm_nt<0,0,1><<<dim3(DD/GBN, BT/GBM), 256>>>(
            ym, DI, W_out + (size_t)l*DD*DI, DI, nullptr, x, x, DD, BT, DD, DI);
        // ln2
        ln_kernel<<<BT, 256>>>(x, ln2_g + l*DD, ln2_b + l*DD, xn);
        // hh = relu(xn @ W_f1^T + b_f1)   (2048 x 2048 x 512)
        sgemm_nt<1,1,0><<<dim3(HH/GBN, BT/GBM), 256>>>(
            xn, DD, W_f1 + (size_t)l*HH*DD, DD, b_f1 + l*HH, nullptr, hh, HH, BT, HH, DD);
        // x += hh @ W_f2^T + b_f2   (2048 x 512 x 2048)
        sgemm_nt<1,0,1><<<dim3(DD/GBN, BT/GBM), 256>>>(
            hh, HH, W_f2 + (size_t)l*DD*HH, HH, b_f2 + l*DD, x, x, DD, BT, DD, HH);
    }

    // logits = x @ lm_w^T + lm_b   (2048 x 32000 x 512)
    sgemm_nt<1,0,0><<<dim3((VV + GBN - 1)/GBN, BT/GBM), 256>>>(
        x, DD, lm_w, DD, lm_b, nullptr, logits, VV, BT, VV, DD);
}

// round 2
// speedup vs baseline: 1.5402x; 1.5402x over previous
#include <cuda_runtime.h>
#include <cuda_bf16.h>
#include <math.h>

// ---------------- problem constants ----------------
#define VV 32000
#define DD 512
#define DI 1024
#define DS 16
#define DC 4
#define DTR 32
#define LL 4
#define HH 2048
#define BB 2
#define TT 1024
#define BT (BB*TT)   // 2048

// ---------------- scratch (static device memory; no allocs allowed) ----------------
__device__ float g_x   [BT*DD];
__device__ float g_xn  [BT*DD];
__device__ float g_xz  [BT*2*DI];
__device__ float g_u   [BT*DI];
__device__ float g_xdbl[BT*64];
__device__ float g_dt  [BT*DI];
__device__ float g_ym  [BT*DI];
__device__ float g_hh  [BT*HH];

// ---------------- embedding ----------------
__global__ void embed_kernel(const int* __restrict__ idx,
                             const float* __restrict__ tok_emb,
                             const float* __restrict__ pos_emb,
                             float* __restrict__ x)
{
    int tid = blockIdx.x * blockDim.x + threadIdx.x;   // BT*DD total
    int d   = tid & (DD-1);
    int tok = tid >> 9;            // b*T + t
    int t   = tok & (TT-1);
    int id  = idx[tok];
    x[tid] = tok_emb[(size_t)id*DD + d] + pos_emb[(size_t)t*DD + d];
}

// ---------------- layer norm (one block per token, 256 threads, D=512) ----------------
__global__ __launch_bounds__(256) void ln_kernel(const float* __restrict__ x,
                                                 const float* __restrict__ gamma,
                                                 const float* __restrict__ beta,
                                                 float* __restrict__ out)
{
    int tok = blockIdx.x;
    const float* xr = x + (size_t)tok * DD;
    int tid = threadIdx.x;
    float v0 = xr[tid], v1 = xr[tid + 256];

    __shared__ float sm[8];
    __shared__ float mv[2];

    float s = v0 + v1;
    #pragma unroll
    for (int o = 16; o; o >>= 1) s += __shfl_xor_sync(0xffffffffu, s, o);
    int w = tid >> 5, ln = tid & 31;
    if (ln == 0) sm[w] = s;
    __syncthreads();
    if (tid == 0) {
        float tot = 0.f;
        #pragma unroll
        for (int i = 0; i < 8; i++) tot += sm[i];
        mv[0] = tot * (1.f / DD);
    }
    __syncthreads();
    float m  = mv[0];
    float d0 = v0 - m, d1 = v1 - m;
    float sq = d0*d0 + d1*d1;
    #pragma unroll
    for (int o = 16; o; o >>= 1) sq += __shfl_xor_sync(0xffffffffu, sq, o);
    if (ln == 0) sm[w] = sq;
    __syncthreads();
    if (tid == 0) {
        float tot = 0.f;
        #pragma unroll
        for (int i = 0; i < 8; i++) tot += sm[i];
        mv[1] = rsqrtf(tot * (1.f / DD) + 1e-5f);
    }
    __syncthreads();
    float rs = mv[1];
    out[(size_t)tok*DD + tid]       = d0 * rs * gamma[tid]       + beta[tid];
    out[(size_t)tok*DD + tid + 256] = d1 * rs * gamma[tid + 256] + beta[tid + 256];
}

// ---------------- causal depthwise conv (DC=4) + silu ----------------
__global__ void conv_silu_kernel(const float* __restrict__ xz,
                                 const float* __restrict__ w,
                                 const float* __restrict__ cb,
                                 float* __restrict__ u)
{
    int tid = blockIdx.x * blockDim.x + threadIdx.x;   // BT*DI
    int i = tid & (DI-1);
    int t = (tid >> 10) & (TT-1);
    int b = tid >> 20;
    float4 wv = *(const float4*)(w + (size_t)i * 4);
    const float* base = xz + ((size_t)(b*TT) + t) * (2*DI) + i;
    float acc = cb[i];
    acc += wv.w * base[0];
    if (t >= 1) acc += wv.z * base[-(2*DI)];
    if (t >= 2) acc += wv.y * base[-2*(2*DI)];
    if (t >= 3) acc += wv.x * base[-3*(2*DI)];
    float sg = 1.f / (1.f + __expf(-acc));
    u[tid] = acc * sg;
}

// ---------------- selective scan: thread per (b,d,s), 16-lane shfl reduce ----------------
__global__ __launch_bounds__(256) void scan_kernel(const float* __restrict__ dt,
                                                   const float* __restrict__ u,
                                                   const float* __restrict__ xdbl,
                                                   const float* __restrict__ xz,
                                                   const float* __restrict__ A_log,
                                                   const float* __restrict__ D_p,
                                                   float* __restrict__ ym)
{
    int tid = blockIdx.x * blockDim.x + threadIdx.x;   // BB*DI*DS = 32768
    int s = tid & (DS-1);
    int d = (tid >> 4) & (DI-1);
    int b = tid >> 14;

    float Ads = -expf(A_log[(size_t)d*DS + s]);
    float Dv  = D_p[d];
    float h = 0.f;

    const float* dt_p = dt   + (size_t)b*TT*DI + d;
    const float* u_p  = u    + (size_t)b*TT*DI + d;
    const float* bd   = xdbl + (size_t)b*TT*64 + DTR + s;
    const float* cd   = xdbl + (size_t)b*TT*64 + DTR + DS + s;
    const float* zp   = xz   + (size_t)b*TT*(2*DI) + DI + d;
    float*       yp   = ym   + (size_t)b*TT*DI + d;

    for (int t = 0; t < TT; t++) {
        float dtv = dt_p[(size_t)t*DI];
        float uv  = u_p [(size_t)t*DI];
        float Bv  = bd  [(size_t)t*64];
        float Cv  = cd  [(size_t)t*64];
        float dA  = __expf(dtv * Ads);
        h = fmaf(dA, h, dtv * uv * Bv);
        float p = h * Cv;
        p += __shfl_xor_sync(0xffffffffu, p, 1);
        p += __shfl_xor_sync(0xffffffffu, p, 2);
        p += __shfl_xor_sync(0xffffffffu, p, 4);
        p += __shfl_xor_sync(0xffffffffu, p, 8);
        if (s == 0) {
            float zv = zp[(size_t)t*(2*DI)];
            float y  = fmaf(uv, Dv, p);
            y = y * (zv / (1.f + __expf(-zv)));
            yp[(size_t)t*DI] = y;
        }
    }
}

// ================= tf32 tensor-core GEMM (NT): C[m,n] = sum_k A[m,k]*B[n,k] =================
// Requires: M%128==0, N%128==0, K%16==0. A row-major lda, B row-major ldb (N x K).
// BIAS: add bias[n]; ACT: 0 none, 1 relu; RES: add res[m,n] after activation.
#define TBM 128
#define TBN 128
#define TBK 16
#define TSTR (TBK + 4)   // padded smem stride (floats): conflict-free fragment loads

__device__ __forceinline__ unsigned cvt_tf32(float x) {
    unsigned r;
    asm("cvt.rna.tf32.f32 %0, %1;" : "=r"(r) : "f"(x));
    return r;
}

__device__ __forceinline__ void mma_tf32(float c[4],
                                         unsigned a0, unsigned a1, unsigned a2, unsigned a3,
                                         unsigned b0, unsigned b1)
{
    asm("mma.sync.aligned.m16n8k8.row.col.f32.tf32.tf32.f32 "
        "{%0,%1,%2,%3}, {%4,%5,%6,%7}, {%8,%9}, {%0,%1,%2,%3};"
        : "+f"(c[0]), "+f"(c[1]), "+f"(c[2]), "+f"(c[3])
        : "r"(a0), "r"(a1), "r"(a2), "r"(a3), "r"(b0), "r"(b1));
}

template<int BIAS, int ACT, int RES>
__global__ __launch_bounds__(256) void tgemm_nt(const float* __restrict__ A, int lda,
                                                const float* __restrict__ Bw, int ldb,
                                                const float* __restrict__ bias,
                                                const float* __restrict__ res,
                                                float* __restrict__ C, int ldc,
                                                int K)
{
    __shared__ unsigned As[TBM][TSTR];
    __shared__ unsigned Bs[TBN][TSTR];

    int tid  = threadIdx.x;
    int m0   = blockIdx.y * TBM;
    int n0   = blockIdx.x * TBN;
    int warp = tid >> 5;
    int lane = tid & 31;
    int warpM = warp & 3;         // 4 warps along M
    int warpN = warp >> 2;        // 2 warps along N
    int grp  = lane >> 2;
    int tig  = lane & 3;

    float acc[2][8][4];
    #pragma unroll
    for (int i = 0; i < 2; i++)
        #pragma unroll
        for (int j = 0; j < 8; j++)
            #pragma unroll
            for (int c = 0; c < 4; c++) acc[i][j][c] = 0.f;

    // gmem loader mapping: 512 float4 per operand tile, 2 per thread
    int id0 = tid, id1 = tid + 256;
    int ar0 = id0 >> 2, ak0 = (id0 & 3) * 4;
    int ar1 = id1 >> 2, ak1 = (id1 & 3) * 4;

    for (int k0 = 0; k0 < K; k0 += TBK) {
        float4 a0 = *(const float4*)(A  + (size_t)(m0 + ar0) * lda + k0 + ak0);
        float4 a1 = *(const float4*)(A  + (size_t)(m0 + ar1) * lda + k0 + ak1);
        float4 b0 = *(const float4*)(Bw + (size_t)(n0 + ar0) * ldb + k0 + ak0);
        float4 b1 = *(const float4*)(Bw + (size_t)(n0 + ar1) * ldb + k0 + ak1);

        __syncthreads();
        As[ar0][ak0+0] = cvt_tf32(a0.x); As[ar0][ak0+1] = cvt_tf32(a0.y);
        As[ar0][ak0+2] = cvt_tf32(a0.z); As[ar0][ak0+3] = cvt_tf32(a0.w);
        As[ar1][ak1+0] = cvt_tf32(a1.x); As[ar1][ak1+1] = cvt_tf32(a1.y);
        As[ar1][ak1+2] = cvt_tf32(a1.z); As[ar1][ak1+3] = cvt_tf32(a1.w);
        Bs[ar0][ak0+0] = cvt_tf32(b0.x); Bs[ar0][ak0+1] = cvt_tf32(b0.y);
        Bs[ar0][ak0+2] = cvt_tf32(b0.z); Bs[ar0][ak0+3] = cvt_tf32(b0.w);
        Bs[ar1][ak1+0] = cvt_tf32(b1.x); Bs[ar1][ak1+1] = cvt_tf32(b1.y);
        Bs[ar1][ak1+2] = cvt_tf32(b1.z); Bs[ar1][ak1+3] = cvt_tf32(b1.w);
        __syncthreads();

        #pragma unroll
        for (int ks = 0; ks < 2; ks++) {
            int kk = ks * 8;
            unsigned af[2][4];
            #pragma unroll
            for (int i = 0; i < 2; i++) {
                int rb = warpM * 32 + i * 16;
                af[i][0] = As[rb + grp    ][kk + tig];
                af[i][1] = As[rb + 8 + grp][kk + tig];
                af[i][2] = As[rb + grp    ][kk + 4 + tig];
                af[i][3] = As[rb + 8 + grp][kk + 4 + tig];
            }
            unsigned bf[8][2];
            #pragma unroll
            for (int j = 0; j < 8; j++) {
                int nb = warpN * 64 + j * 8;
                bf[j][0] = Bs[nb + grp][kk + tig];
                bf[j][1] = Bs[nb + grp][kk + 4 + tig];
            }
            #pragma unroll
            for (int i = 0; i < 2; i++)
                #pragma unroll
                for (int j = 0; j < 8; j++)
                    mma_tf32(acc[i][j], af[i][0], af[i][1], af[i][2], af[i][3],
                             bf[j][0], bf[j][1]);
        }
    }

    // epilogue: each acc[i][j] is a 16x8 tile; c0,c1 at (grp, 2*tig), c2,c3 at (grp+8, 2*tig)
    #pragma unroll
    for (int i = 0; i < 2; i++) {
        int rbase = m0 + warpM * 32 + i * 16 + grp;
        #pragma unroll
        for (int j = 0; j < 8; j++) {
            int n = n0 + warpN * 64 + j * 8 + tig * 2;
            float bv0 = 0.f, bv1 = 0.f;
            if (BIAS) { bv0 = bias[n]; bv1 = bias[n+1]; }
            #pragma unroll
            for (int h = 0; h < 2; h++) {
                int m = rbase + h * 8;
                float v0 = acc[i][j][2*h+0] + bv0;
                float v1 = acc[i][j][2*h+1] + bv1;
                if (ACT == 1) { v0 = fmaxf(v0, 0.f); v1 = fmaxf(v1, 0.f); }
                if (RES) {
                    float2 r = *(const float2*)(res + (size_t)m * ldc + n);
                    v0 += r.x; v1 += r.y;
                }
                *(float2*)(C + (size_t)m * ldc + n) = make_float2(v0, v1);
            }
        }
    }
}

// ---------------- fp32 SIMT GEMM (NT) for small/odd shapes ----------------
#define GBM 128
#define GBN 128
#define GBK 8

__device__ __forceinline__ unsigned long long pack_dup(float a) {
    unsigned long long r;
    asm("mov.b64 %0, {%1, %1};" : "=l"(r) : "f"(a));
    return r;
}

template<int BIAS, int ACT, int RES>
__global__ __launch_bounds__(256) void sgemm_nt(const float* __restrict__ A, int lda,
                                                const float* __restrict__ Bw, int ldb,
                                                const float* __restrict__ bias,
                                                const float* __restrict__ res,
                                                float* __restrict__ C, int ldc,
                                                int M, int N, int K)
{
    __shared__ float As[GBK][GBM];
    __shared__ float Bs[GBK][GBN];

    int tid = threadIdx.x;
    int m0 = blockIdx.y * GBM;
    int n0 = blockIdx.x * GBN;

    int loadRow = tid >> 1;
    int loadK4  = (tid & 1) * 4;

    int tx = tid & 15, ty = tid >> 4;
    int row0 = ty * 8, col0 = tx * 8;

    unsigned long long acc[8][4];
    #pragma unroll
    for (int i = 0; i < 8; i++)
        #pragma unroll
        for (int j = 0; j < 4; j++) acc[i][j] = 0ULL;

    for (int k0 = 0; k0 < K; k0 += GBK) {
        float4 av = *(const float4*)(A + (size_t)(m0 + loadRow) * lda + k0 + loadK4);
        float4 bv = make_float4(0.f, 0.f, 0.f, 0.f);
        int nrow = n0 + loadRow;
        if (nrow < N)
            bv = *(const float4*)(Bw + (size_t)nrow * ldb + k0 + loadK4);

        __syncthreads();
        As[loadK4+0][loadRow] = av.x;
        As[loadK4+1][loadRow] = av.y;
        As[loadK4+2][loadRow] = av.z;
        As[loadK4+3][loadRow] = av.w;
        Bs[loadK4+0][loadRow] = bv.x;
        Bs[loadK4+1][loadRow] = bv.y;
        Bs[loadK4+2][loadRow] = bv.z;
        Bs[loadK4+3][loadRow] = bv.w;
        __syncthreads();

        #pragma unroll
        for (int kk = 0; kk < GBK; kk++) {
            float a[8];
            *(float4*)&a[0] = *(const float4*)&As[kk][row0];
            *(float4*)&a[4] = *(const float4*)&As[kk][row0 + 4];
            unsigned long long b2[4];
            const unsigned long long* bp = (const unsigned long long*)&Bs[kk][col0];
            b2[0] = bp[0]; b2[1] = bp[1]; b2[2] = bp[2]; b2[3] = bp[3];
            #pragma unroll
            for (int i = 0; i < 8; i++) {
                unsigned long long aa = pack_dup(a[i]);
                #pragma unroll
                for (int j = 0; j < 4; j++)
                    asm("fma.rn.f32x2 %0, %1, %2, %0;" : "+l"(acc[i][j]) : "l"(aa), "l"(b2[j]));
            }
        }
    }

    #pragma unroll
    for (int i = 0; i < 8; i++) {
        int m = m0 + row0 + i;
        float vr[8];
        #pragma unroll
        for (int j = 0; j < 4; j++)
            asm("mov.b64 {%0, %1}, %2;" : "=f"(vr[2*j]), "=f"(vr[2*j+1]) : "l"(acc[i][j]));
        #pragma unroll
        for (int j = 0; j < 8; j++) {
            int n = n0 + col0 + j;
            if (n < N) {
                float v = vr[j];
                if (BIAS) v += bias[n];
                if (ACT == 1) v = fmaxf(v, 0.f);
                if (ACT == 2) v = (v > 20.f) ? v : log1pf(expf(v));
                if (RES) v += res[(size_t)m * ldc + n];
                C[(size_t)m * ldc + n] = v;
            }
        }
    }
}

// ---------------- launch ----------------
extern "C" void kernel_launch(void* const* d_in, const int* in_sizes, int n_in,
                              void* d_out, int out_size)
{
    const int*   idx     = (const int*)  d_in[0];
    const float* tok_emb = (const float*)d_in[1];
    const float* pos_emb = (const float*)d_in[2];
    const float* ln1_g   = (const float*)d_in[3];
    const float* ln1_b   = (const float*)d_in[4];
    const float* W_in    = (const float*)d_in[5];
    const float* conv_w  = (const float*)d_in[6];
    const float* conv_b  = (const float*)d_in[7];
    const float* W_xp    = (const float*)d_in[8];
    const float* W_dt    = (const float*)d_in[9];
    const float* b_dt    = (const float*)d_in[10];
    const float* A_log   = (const float*)d_in[11];
    const float* D_p     = (const float*)d_in[12];
    const float* W_out   = (const float*)d_in[13];
    const float* ln2_g   = (const float*)d_in[14];
    const float* ln2_b   = (const float*)d_in[15];
    const float* W_f1    = (const float*)d_in[16];
    const float* b_f1    = (const float*)d_in[17];
    const float* W_f2    = (const float*)d_in[18];
    const float* b_f2    = (const float*)d_in[19];
    const float* lm_w    = (const float*)d_in[20];
    const float* lm_b    = (const float*)d_in[21];
    float* logits = (float*)d_out;

    float *x, *xn, *xz, *u, *xdbl, *dt, *ym, *hh;
    cudaGetSymbolAddress((void**)&x,    g_x);
    cudaGetSymbolAddress((void**)&xn,   g_xn);
    cudaGetSymbolAddress((void**)&xz,   g_xz);
    cudaGetSymbolAddress((void**)&u,    g_u);
    cudaGetSymbolAddress((void**)&xdbl, g_xdbl);
    cudaGetSymbolAddress((void**)&dt,   g_dt);
    cudaGetSymbolAddress((void**)&ym,   g_ym);
    cudaGetSymbolAddress((void**)&hh,   g_hh);

    embed_kernel<<<(BT*DD)/256, 256>>>(idx, tok_emb, pos_emb, x);

    for (int l = 0; l < LL; l++) {
        // ln1
        ln_kernel<<<BT, 256>>>(x, ln1_g + l*DD, ln1_b + l*DD, xn);
        // xz = xn @ W_in^T   (2048 x 2048 x 512) — tensor cores
        tgemm_nt<0,0,0><<<dim3(2*DI/TBN, BT/TBM), 256>>>(
            xn, DD, W_in + (size_t)l*2*DI*DD, DD, nullptr, nullptr, xz, 2*DI, DD);
        // depthwise conv + silu -> u
        conv_silu_kernel<<<(BT*DI)/256, 256>>>(xz, conv_w + (size_t)l*DI*DC, conv_b + l*DI, u);
        // x_dbl = u @ W_xp^T   (2048 x 64 x 1024) — small, SIMT
        sgemm_nt<0,0,0><<<dim3(1, BT/GBM), 256>>>(
            u, DI, W_xp + (size_t)l*64*DI, DI, nullptr, nullptr, xdbl, 64, BT, 64, DI);
        // dt = softplus(x_dbl[:, :32] @ W_dt^T + b_dt)   (2048 x 1024 x 32) — small K, SIMT
        sgemm_nt<1,2,0><<<dim3(DI/GBN, BT/GBM), 256>>>(
            xdbl, 64, W_dt + (size_t)l*DI*DTR, DTR, b_dt + l*DI, nullptr, dt, DI, BT, DI, DTR);
        // selective scan -> ym (fused +u*D_p and *silu(z))
        scan_kernel<<<(BB*DI*DS)/256, 256>>>(dt, u, xdbl, xz,
                                             A_log + (size_t)l*DI*DS, D_p + l*DI, ym);
        // x += ym @ W_out^T   (2048 x 512 x 1024) — tensor cores
        tgemm_nt<0,0,1><<<dim3(DD/TBN, BT/TBM), 256>>>(
            ym, DI, W_out + (size_t)l*DD*DI, DI, nullptr, x, x, DD, DI);
        // ln2
        ln_kernel<<<BT, 256>>>(x, ln2_g + l*DD, ln2_b + l*DD, xn);
        // hh = relu(xn @ W_f1^T + b_f1)   (2048 x 2048 x 512) — tensor cores
        tgemm_nt<1,1,0><<<dim3(HH/TBN, BT/TBM), 256>>>(
            xn, DD, W_f1 + (size_t)l*HH*DD, DD, b_f1 + l*HH, nullptr, hh, HH, DD);
        // x += hh @ W_f2^T + b_f2   (2048 x 512 x 2048) — tensor cores
        tgemm_nt<1,0,1><<<dim3(DD/TBN, BT/TBM), 256>>>(
            hh, HH, W_f2 + (size_t)l*DD*HH, HH, b_f2 + l*DD, x, x, DD, HH);
    }

    // logits = x @ lm_w^T + lm_b   (2048 x 32000 x 512) — tensor cores, N=32000=250*128
    tgemm_nt<1,0,0><<<dim3(VV/TBN, BT/TBM), 256>>>(
        x, DD, lm_w, DD, lm_b, nullptr, logits, VV, DD);
}

// round 4
// speedup vs baseline: 1.6644x; 1.0806x over previous
#include <cuda_runtime.h>
#include <cuda_bf16.h>
#include <cstdint>
#include <math.h>

// ---------------- problem constants ----------------
#define VV 32000
#define DD 512
#define DI 1024
#define DS 16
#define DC 4
#define DTR 32
#define LL 4
#define HH 2048
#define BB 2
#define TT 1024
#define BT (BB*TT)   // 2048

// ---------------- scratch (static device memory; no allocs allowed) ----------------
__device__ float g_x   [BT*DD];
__device__ float g_xn  [BT*DD];
__device__ float g_xz  [BT*2*DI];
__device__ float g_u   [BT*DI];
__device__ float g_xdbl[BT*64];
__device__ float g_dt  [BT*DI];
__device__ float g_ym  [BT*DI];
__device__ float g_hh  [BT*HH];
// tf32-rounded weight copies
__device__ float g_wt_in [LL*2*DI*DD];
__device__ float g_wt_out[LL*DD*DI];
__device__ float g_wt_f1 [LL*HH*DD];
__device__ float g_wt_f2 [LL*DD*HH];
__device__ float g_wt_lm [VV*DD];

// ---------------- helpers ----------------
__device__ __forceinline__ uint32_t smem_u32(const void* p) {
    uint32_t a;
    asm("{ .reg .u64 t; cvta.to.shared.u64 t, %1; cvt.u32.u64 %0, t; }" : "=r"(a) : "l"(p));
    return a;
}
__device__ __forceinline__ unsigned cvt_tf32(float x) {
    unsigned r;
    asm("cvt.rna.tf32.f32 %0, %1;" : "=r"(r) : "f"(x));
    return r;
}
__device__ __forceinline__ float rna_tf32f(float x) { return __uint_as_float(cvt_tf32(x)); }

__device__ __forceinline__ void mma_tf32(float c[4],
                                         unsigned a0, unsigned a1, unsigned a2, unsigned a3,
                                         unsigned b0, unsigned b1)
{
    asm("mma.sync.aligned.m16n8k8.row.col.f32.tf32.tf32.f32 "
        "{%0,%1,%2,%3}, {%4,%5,%6,%7}, {%8,%9}, {%0,%1,%2,%3};"
        : "+f"(c[0]), "+f"(c[1]), "+f"(c[2]), "+f"(c[3])
        : "r"(a0), "r"(a1), "r"(a2), "r"(a3), "r"(b0), "r"(b1));
}

// ===== pipelined tf32 mma.sync GEMM (NT): C[m,n] = sum_k A[m,k]*B[n,k] =====
// Block tile 128x128, K-block 16, 4-stage cp.async pipeline, 8 warps (32x64 each).
// Requires M%128==0, N%128==0, K%16==0. Operands assumed pre-rounded to tf32 grid.
#define PBM 128
#define PBK 16
#define PSTR 20                          // padded row stride (floats) — all-bank-distinct
#define OP_FLOATS (PBM*PSTR)             // 2560 floats per operand per stage
#define STAGE_FLOATS (2*OP_FLOATS)       // A then B
#define PSTAGES 4
#define PIPE_SMEM (PSTAGES*STAGE_FLOATS*4)   // 81920 B

template<int BIAS, int ACT, int RES, int CVTOUT>
__global__ __launch_bounds__(256) void pgemm_nt(
    const float* __restrict__ A, int lda,
    const float* __restrict__ Bw, int ldb,
    const float* __restrict__ bias,
    const float* __restrict__ res,
    float* __restrict__ C, int ldc, int K)
{
    extern __shared__ float smf[];
    uint32_t sb = smem_u32(smf);

    int tid  = threadIdx.x;
    int m0   = blockIdx.y * PBM;
    int n0   = blockIdx.x * PBM;
    int warp = tid >> 5;
    int lane = tid & 31;
    int warpM = warp & 3;         // 4 warps along M (32 rows each)
    int warpN = warp >> 2;        // 2 warps along N (64 cols each)
    int grp  = lane >> 2;         // 0..7
    int tig  = lane & 3;          // 0..3

    // loader mapping: per operand 512 float4 chunks; ids tid and tid+256
    int r0 = tid >> 1;            // rows 0..127 (ids 0..255)
    int q0 = (tid & 1) * 2;       // float4 index 0 or 2  -> covers q 0..3 via 2 ids
    // simpler: id0 = tid -> row=tid>>1? That gives 2 float4/row for 16 floats/row (4 float4).
    // Use: id in [0,512): row = id>>2, q = id&3. Thread handles id0=tid, id1=tid+256.
    int idA0 = tid,        rA0 = idA0 >> 2, qA0 = idA0 & 3;
    int idA1 = tid + 256,  rA1 = idA1 >> 2, qA1 = idA1 & 3;
    (void)r0; (void)q0;

    int KB = K >> 4;   // number of 16-deep k-blocks

    auto load_stage = [&](int stage, int kb) {
        uint32_t base = sb + (uint32_t)stage * (STAGE_FLOATS * 4);
        if (kb < KB) {
            int k0 = kb << 4;
            const float* pa0 = A  + (size_t)(m0 + rA0) * lda + k0 + qA0 * 4;
            const float* pa1 = A  + (size_t)(m0 + rA1) * lda + k0 + qA1 * 4;
            const float* pb0 = Bw + (size_t)(n0 + rA0) * ldb + k0 + qA0 * 4;
            const float* pb1 = Bw + (size_t)(n0 + rA1) * ldb + k0 + qA1 * 4;
            uint32_t da0 = base + (uint32_t)(rA0 * PSTR + qA0 * 4) * 4;
            uint32_t da1 = base + (uint32_t)(rA1 * PSTR + qA1 * 4) * 4;
            uint32_t db0 = base + (uint32_t)(OP_FLOATS + rA0 * PSTR + qA0 * 4) * 4;
            uint32_t db1 = base + (uint32_t)(OP_FLOATS + rA1 * PSTR + qA1 * 4) * 4;
            asm volatile("cp.async.cg.shared.global [%0], [%1], 16;" :: "r"(da0), "l"(pa0));
            asm volatile("cp.async.cg.shared.global [%0], [%1], 16;" :: "r"(da1), "l"(pa1));
            asm volatile("cp.async.cg.shared.global [%0], [%1], 16;" :: "r"(db0), "l"(pb0));
            asm volatile("cp.async.cg.shared.global [%0], [%1], 16;" :: "r"(db1), "l"(pb1));
        }
        asm volatile("cp.async.commit_group;" ::: "memory");
    };

    float acc[2][8][4];
    #pragma unroll
    for (int i = 0; i < 2; i++)
        #pragma unroll
        for (int j = 0; j < 8; j++)
            #pragma unroll
            for (int c = 0; c < 4; c++) acc[i][j][c] = 0.f;

    // prologue: prefetch 3 stages
    #pragma unroll
    for (int s = 0; s < PSTAGES - 1; s++) load_stage(s, s);

    const unsigned* smu = (const unsigned*)smf;

    for (int kb = 0; kb < KB; kb++) {
        asm volatile("cp.async.wait_group %0;" :: "n"(PSTAGES - 2) : "memory");
        __syncthreads();

        // issue next stage's loads early (stage (kb-1)%4 was consumed in iter kb-1)
        load_stage((kb + PSTAGES - 1) % PSTAGES, kb + PSTAGES - 1);

        const unsigned* st = smu + ((kb % PSTAGES) * STAGE_FLOATS);
        const unsigned* sa = st;
        const unsigned* sbp = st + OP_FLOATS;

        #pragma unroll
        for (int ks = 0; ks < 2; ks++) {
            int kk = ks * 8;
            unsigned af[2][4];
            #pragma unroll
            for (int i = 0; i < 2; i++) {
                int rb = warpM * 32 + i * 16;
                af[i][0] = sa[(rb + grp)     * PSTR + kk + tig];
                af[i][1] = sa[(rb + 8 + grp) * PSTR + kk + tig];
                af[i][2] = sa[(rb + grp)     * PSTR + kk + 4 + tig];
                af[i][3] = sa[(rb + 8 + grp) * PSTR + kk + 4 + tig];
            }
            unsigned bf[8][2];
            #pragma unroll
            for (int j = 0; j < 8; j++) {
                int nb = warpN * 64 + j * 8;
                bf[j][0] = sbp[(nb + grp) * PSTR + kk + tig];
                bf[j][1] = sbp[(nb + grp) * PSTR + kk + 4 + tig];
            }
            #pragma unroll
            for (int i = 0; i < 2; i++)
                #pragma unroll
                for (int j = 0; j < 8; j++)
                    mma_tf32(acc[i][j], af[i][0], af[i][1], af[i][2], af[i][3],
                             bf[j][0], bf[j][1]);
        }
        __syncthreads();
    }

    // epilogue
    #pragma unroll
    for (int i = 0; i < 2; i++) {
        int rbase = m0 + warpM * 32 + i * 16 + grp;
        #pragma unroll
        for (int j = 0; j < 8; j++) {
            int n = n0 + warpN * 64 + j * 8 + tig * 2;
            float bv0 = 0.f, bv1 = 0.f;
            if (BIAS) { bv0 = bias[n]; bv1 = bias[n+1]; }
            #pragma unroll
            for (int h = 0; h < 2; h++) {
                int m = rbase + h * 8;
                float v0 = acc[i][j][2*h+0] + bv0;
                float v1 = acc[i][j][2*h+1] + bv1;
                if (ACT == 1) { v0 = fmaxf(v0, 0.f); v1 = fmaxf(v1, 0.f); }
                if (RES) {
                    float2 r = *(const float2*)(res + (size_t)m * ldc + n);
                    v0 += r.x; v1 += r.y;
                }
                if (CVTOUT) { v0 = rna_tf32f(v0); v1 = rna_tf32f(v1); }
                *(float2*)(C + (size_t)m * ldc + n) = make_float2(v0, v1);
            }
        }
    }
}

// ---------------- tf32 rounding conversion (weights / lm input) ----------------
__global__ void cvt_tf32_kernel(const float4* __restrict__ src, float4* __restrict__ dst, int n4)
{
    int i = blockIdx.x * blockDim.x + threadIdx.x;
    if (i < n4) {
        float4 v = src[i];
        v.x = rna_tf32f(v.x); v.y = rna_tf32f(v.y);
        v.z = rna_tf32f(v.z); v.w = rna_tf32f(v.w);
        dst[i] = v;
    }
}

// ---------------- embedding ----------------
__global__ void embed_kernel(const int* __restrict__ idx,
                             const float* __restrict__ tok_emb,
                             const float* __restrict__ pos_emb,
                             float* __restrict__ x)
{
    int tid = blockIdx.x * blockDim.x + threadIdx.x;
    int d   = tid & (DD-1);
    int tok = tid >> 9;
    int t   = tok & (TT-1);
    int id  = idx[tok];
    x[tid] = tok_emb[(size_t)id*DD + d] + pos_emb[(size_t)t*DD + d];
}

// ---------------- layer norm (out rounded to tf32 — feeds tensor GEMMs only) ----------------
__global__ __launch_bounds__(256) void ln_kernel(const float* __restrict__ x,
                                                 const float* __restrict__ gamma,
                                                 const float* __restrict__ beta,
                                                 float* __restrict__ out)
{
    int tok = blockIdx.x;
    const float* xr = x + (size_t)tok * DD;
    int tid = threadIdx.x;
    float v0 = xr[tid], v1 = xr[tid + 256];

    __shared__ float sm[8];
    __shared__ float mv[2];

    float s = v0 + v1;
    #pragma unroll
    for (int o = 16; o; o >>= 1) s += __shfl_xor_sync(0xffffffffu, s, o);
    int w = tid >> 5, ln = tid & 31;
    if (ln == 0) sm[w] = s;
    __syncthreads();
    if (tid == 0) {
        float tot = 0.f;
        #pragma unroll
        for (int i = 0; i < 8; i++) tot += sm[i];
        mv[0] = tot * (1.f / DD);
    }
    __syncthreads();
    float m  = mv[0];
    float d0 = v0 - m, d1 = v1 - m;
    float sq = d0*d0 + d1*d1;
    #pragma unroll
    for (int o = 16; o; o >>= 1) sq += __shfl_xor_sync(0xffffffffu, sq, o);
    if (ln == 0) sm[w] = sq;
    __syncthreads();
    if (tid == 0) {
        float tot = 0.f;
        #pragma unroll
        for (int i = 0; i < 8; i++) tot += sm[i];
        mv[1] = rsqrtf(tot * (1.f / DD) + 1e-5f);
    }
    __syncthreads();
    float rs = mv[1];
    out[(size_t)tok*DD + tid]       = rna_tf32f(d0 * rs * gamma[tid]       + beta[tid]);
    out[(size_t)tok*DD + tid + 256] = rna_tf32f(d1 * rs * gamma[tid + 256] + beta[tid + 256]);
}

// ---------------- causal depthwise conv (DC=4) + silu ----------------
__global__ void conv_silu_kernel(const float* __restrict__ xz,
                                 const float* __restrict__ w,
                                 const float* __restrict__ cb,
                                 float* __restrict__ u)
{
    int tid = blockIdx.x * blockDim.x + threadIdx.x;
    int i = tid & (DI-1);
    int t = (tid >> 10) & (TT-1);
    int b = tid >> 20;
    float4 wv = *(const float4*)(w + (size_t)i * 4);
    const float* base = xz + ((size_t)(b*TT) + t) * (2*DI) + i;
    float acc = cb[i];
    acc += wv.w * base[0];
    if (t >= 1) acc += wv.z * base[-(2*DI)];
    if (t >= 2) acc += wv.y * base[-2*(2*DI)];
    if (t >= 3) acc += wv.x * base[-3*(2*DI)];
    float sg = 1.f / (1.f + __expf(-acc));
    u[tid] = acc * sg;
}

// ---------------- selective scan (ym rounded — feeds W_out tensor GEMM only) ----------------
__global__ __launch_bounds__(256) void scan_kernel(const float* __restrict__ dt,
                                                   const float* __restrict__ u,
                                                   const float* __restrict__ xdbl,
                                                   const float* __restrict__ xz,
                                                   const float* __restrict__ A_log,
                                                   const float* __restrict__ D_p,
                                                   float* __restrict__ ym)
{
    int tid = blockIdx.x * blockDim.x + threadIdx.x;
    int s = tid & (DS-1);
    int d = (tid >> 4) & (DI-1);
    int b = tid >> 14;

    float Ads = -expf(A_log[(size_t)d*DS + s]);
    float Dv  = D_p[d];
    float h = 0.f;

    const float* dt_p = dt   + (size_t)b*TT*DI + d;
    const float* u_p  = u    + (size_t)b*TT*DI + d;
    const float* bd   = xdbl + (size_t)b*TT*64 + DTR + s;
    const float* cd   = xdbl + (size_t)b*TT*64 + DTR + DS + s;
    const float* zp   = xz   + (size_t)b*TT*(2*DI) + DI + d;
    float*       yp   = ym   + (size_t)b*TT*DI + d;

    for (int t = 0; t < TT; t++) {
        float dtv = dt_p[(size_t)t*DI];
        float uv  = u_p [(size_t)t*DI];
        float Bv  = bd  [(size_t)t*64];
        float Cv  = cd  [(size_t)t*64];
        float dA  = __expf(dtv * Ads);
        h = fmaf(dA, h, dtv * uv * Bv);
        float p = h * Cv;
        p += __shfl_xor_sync(0xffffffffu, p, 1);
        p += __shfl_xor_sync(0xffffffffu, p, 2);
        p += __shfl_xor_sync(0xffffffffu, p, 4);
        p += __shfl_xor_sync(0xffffffffu, p, 8);
        if (s == 0) {
            float zv = zp[(size_t)t*(2*DI)];
            float y  = fmaf(uv, Dv, p);
            y = y * (zv / (1.f + __expf(-zv)));
            yp[(size_t)t*DI] = rna_tf32f(y);
        }
    }
}

// ---------------- fp32 SIMT GEMM (NT) for small shapes (W_xp, W_dt) ----------------
#define GBM 128
#define GBN 128
#define GBK 8

__device__ __forceinline__ unsigned long long pack_dup(float a) {
    unsigned long long r;
    asm("mov.b64 %0, {%1, %1};" : "=l"(r) : "f"(a));
    return r;
}

template<int BIAS, int ACT, int RES>
__global__ __launch_bounds__(256) void sgemm_nt(const float* __restrict__ A, int lda,
                                                const float* __restrict__ Bw, int ldb,
                                                const float* __restrict__ bias,
                                                const float* __restrict__ res,
                                                float* __restrict__ C, int ldc,
                                                int M, int N, int K)
{
    __shared__ float As[GBK][GBM];
    __shared__ float Bs[GBK][GBN];

    int tid = threadIdx.x;
    int m0 = blockIdx.y * GBM;
    int n0 = blockIdx.x * GBN;

    int loadRow = tid >> 1;
    int loadK4  = (tid & 1) * 4;

    int tx = tid & 15, ty = tid >> 4;
    int row0 = ty * 8, col0 = tx * 8;

    unsigned long long acc[8][4];
    #pragma unroll
    for (int i = 0; i < 8; i++)
        #pragma unroll
        for (int j = 0; j < 4; j++) acc[i][j] = 0ULL;

    for (int k0 = 0; k0 < K; k0 += GBK) {
        float4 av = *(const float4*)(A + (size_t)(m0 + loadRow) * lda + k0 + loadK4);
        float4 bv = make_float4(0.f, 0.f, 0.f, 0.f);
        int nrow = n0 + loadRow;
        if (nrow < N)
            bv = *(const float4*)(Bw + (size_t)nrow * ldb + k0 + loadK4);

        __syncthreads();
        As[loadK4+0][loadRow] = av.x;
        As[loadK4+1][loadRow] = av.y;
        As[loadK4+2][loadRow] = av.z;
        As[loadK4+3][loadRow] = av.w;
        Bs[loadK4+0][loadRow] = bv.x;
        Bs[loadK4+1][loadRow] = bv.y;
        Bs[loadK4+2][loadRow] = bv.z;
        Bs[loadK4+3][loadRow] = bv.w;
        __syncthreads();

        #pragma unroll
        for (int kk = 0; kk < GBK; kk++) {
            float a[8];
            *(float4*)&a[0] = *(const float4*)&As[kk][row0];
            *(float4*)&a[4] = *(const float4*)&As[kk][row0 + 4];
            unsigned long long b2[4];
            const unsigned long long* bp = (const unsigned long long*)&Bs[kk][col0];
            b2[0] = bp[0]; b2[1] = bp[1]; b2[2] = bp[2]; b2[3] = bp[3];
            #pragma unroll
            for (int i = 0; i < 8; i++) {
                unsigned long long aa = pack_dup(a[i]);
                #pragma unroll
                for (int j = 0; j < 4; j++)
                    asm("fma.rn.f32x2 %0, %1, %2, %0;" : "+l"(acc[i][j]) : "l"(aa), "l"(b2[j]));
            }
        }
    }

    #pragma unroll
    for (int i = 0; i < 8; i++) {
        int m = m0 + row0 + i;
        float vr[8];
        #pragma unroll
        for (int j = 0; j < 4; j++)
            asm("mov.b64 {%0, %1}, %2;" : "=f"(vr[2*j]), "=f"(vr[2*j+1]) : "l"(acc[i][j]));
        #pragma unroll
        for (int j = 0; j < 8; j++) {
            int n = n0 + col0 + j;
            if (n < N) {
                float v = vr[j];
                if (BIAS) v += bias[n];
                if (ACT == 1) v = fmaxf(v, 0.f);
                if (ACT == 2) v = (v > 20.f) ? v : log1pf(expf(v));
                if (RES) v += res[(size_t)m * ldc + n];
                C[(size_t)m * ldc + n] = v;
            }
        }
    }
}

// ---------------- launch ----------------
extern "C" void kernel_launch(void* const* d_in, const int* in_sizes, int n_in,
                              void* d_out, int out_size)
{
    const int*   idx     = (const int*)  d_in[0];
    const float* tok_emb = (const float*)d_in[1];
    const float* pos_emb = (const float*)d_in[2];
    const float* ln1_g   = (const float*)d_in[3];
    const float* ln1_b   = (const float*)d_in[4];
    const float* W_in    = (const float*)d_in[5];
    const float* conv_w  = (const float*)d_in[6];
    const float* conv_b  = (const float*)d_in[7];
    const float* W_xp    = (const float*)d_in[8];
    const float* W_dt    = (const float*)d_in[9];
    const float* b_dt    = (const float*)d_in[10];
    const float* A_log   = (const float*)d_in[11];
    const float* D_p     = (const float*)d_in[12];
    const float* W_out   = (const float*)d_in[13];
    const float* ln2_g   = (const float*)d_in[14];
    const float* ln2_b   = (const float*)d_in[15];
    const float* W_f1    = (const float*)d_in[16];
    const float* b_f1    = (const float*)d_in[17];
    const float* W_f2    = (const float*)d_in[18];
    const float* b_f2    = (const float*)d_in[19];
    const float* lm_w    = (const float*)d_in[20];
    const float* lm_b    = (const float*)d_in[21];
    float* logits = (float*)d_out;

    float *x, *xn, *xz, *u, *xdbl, *dt, *ym, *hh;
    float *wt_in, *wt_out, *wt_f1, *wt_f2, *wt_lm;
    cudaGetSymbolAddress((void**)&x,     g_x);
    cudaGetSymbolAddress((void**)&xn,    g_xn);
    cudaGetSymbolAddress((void**)&xz,    g_xz);
    cudaGetSymbolAddress((void**)&u,     g_u);
    cudaGetSymbolAddress((void**)&xdbl,  g_xdbl);
    cudaGetSymbolAddress((void**)&dt,    g_dt);
    cudaGetSymbolAddress((void**)&ym,    g_ym);
    cudaGetSymbolAddress((void**)&hh,    g_hh);
    cudaGetSymbolAddress((void**)&wt_in, g_wt_in);
    cudaGetSymbolAddress((void**)&wt_out,g_wt_out);
    cudaGetSymbolAddress((void**)&wt_f1, g_wt_f1);
    cudaGetSymbolAddress((void**)&wt_f2, g_wt_f2);
    cudaGetSymbolAddress((void**)&wt_lm, g_wt_lm);

    // raise dynamic smem limit for all pgemm instantiations (idempotent)
    cudaFuncSetAttribute(pgemm_nt<0,0,0,0>, cudaFuncAttributeMaxDynamicSharedMemorySize, PIPE_SMEM);
    cudaFuncSetAttribute(pgemm_nt<0,0,1,0>, cudaFuncAttributeMaxDynamicSharedMemorySize, PIPE_SMEM);
    cudaFuncSetAttribute(pgemm_nt<1,1,0,1>, cudaFuncAttributeMaxDynamicSharedMemorySize, PIPE_SMEM);
    cudaFuncSetAttribute(pgemm_nt<1,0,1,0>, cudaFuncAttributeMaxDynamicSharedMemorySize, PIPE_SMEM);
    cudaFuncSetAttribute(pgemm_nt<1,0,0,0>, cudaFuncAttributeMaxDynamicSharedMemorySize, PIPE_SMEM);

    // weight conversions to rna-rounded tf32 scratch
    cvt_tf32_kernel<<<(LL*2*DI*DD/4 + 255)/256, 256>>>((const float4*)W_in,  (float4*)wt_in,  LL*2*DI*DD/4);
    cvt_tf32_kernel<<<(LL*DD*DI/4   + 255)/256, 256>>>((const float4*)W_out, (float4*)wt_out, LL*DD*DI/4);
    cvt_tf32_kernel<<<(LL*HH*DD/4   + 255)/256, 256>>>((const float4*)W_f1,  (float4*)wt_f1,  LL*HH*DD/4);
    cvt_tf32_kernel<<<(LL*DD*HH/4   + 255)/256, 256>>>((const float4*)W_f2,  (float4*)wt_f2,  LL*DD*HH/4);
    cvt_tf32_kernel<<<(VV*DD/4      + 255)/256, 256>>>((const float4*)lm_w,  (float4*)wt_lm,  VV*DD/4);

    embed_kernel<<<(BT*DD)/256, 256>>>(idx, tok_emb, pos_emb, x);

    for (int l = 0; l < LL; l++) {
        // ln1 (rounded output)
        ln_kernel<<<BT, 256>>>(x, ln1_g + l*DD, ln1_b + l*DD, xn);
        // xz = xn @ W_in^T   (2048 x 2048 x 512)
        pgemm_nt<0,0,0,0><<<dim3(2*DI/128, BT/128), 256, PIPE_SMEM>>>(
            xn, DD, wt_in + (size_t)l*2*DI*DD, DD, nullptr, nullptr, xz, 2*DI, DD);
        // depthwise conv + silu -> u (fp32)
        conv_silu_kernel<<<(BT*DI)/256, 256>>>(xz, conv_w + (size_t)l*DI*DC, conv_b + l*DI, u);
        // x_dbl = u @ W_xp^T   (2048 x 64 x 1024) — SIMT fp32
        sgemm_nt<0,0,0><<<dim3(1, BT/GBM), 256>>>(
            u, DI, W_xp + (size_t)l*64*DI, DI, nullptr, nullptr, xdbl, 64, BT, 64, DI);
        // dt = softplus(x_dbl[:, :32] @ W_dt^T + b_dt) — SIMT fp32
        sgemm_nt<1,2,0><<<dim3(DI/GBN, BT/GBM), 256>>>(
            xdbl, 64, W_dt + (size_t)l*DI*DTR, DTR, b_dt + l*DI, nullptr, dt, DI, BT, DI, DTR);
        // selective scan -> ym (rounded output)
        scan_kernel<<<(BB*DI*DS)/256, 256>>>(dt, u, xdbl, xz,
                                             A_log + (size_t)l*DI*DS, D_p + l*DI, ym);
        // x += ym @ W_out^T   (2048 x 512 x 1024)
        pgemm_nt<0,0,1,0><<<dim3(DD/128, BT/128), 256, PIPE_SMEM>>>(
            ym, DI, wt_out + (size_t)l*DD*DI, DI, nullptr, x, x, DD, DI);
        // ln2 (rounded output)
        ln_kernel<<<BT, 256>>>(x, ln2_g + l*DD, ln2_b + l*DD, xn);
        // hh = relu(xn @ W_f1^T + b_f1)  (2048 x 2048 x 512), rounded output
        pgemm_nt<1,1,0,1><<<dim3(HH/128, BT/128), 256, PIPE_SMEM>>>(
            xn, DD, wt_f1 + (size_t)l*HH*DD, DD, b_f1 + l*HH, nullptr, hh, HH, DD);
        // x += hh @ W_f2^T + b_f2   (2048 x 512 x 2048)
        pgemm_nt<1,0,1,0><<<dim3(DD/128, BT/128), 256, PIPE_SMEM>>>(
            hh, HH, wt_f2 + (size_t)l*DD*HH, HH, b_f2 + l*DD, x, x, DD, HH);
    }

    // lm input rounded into xn, then logits = xn @ lm_w^T + lm_b  (2048 x 32000 x 512)
    cvt_tf32_kernel<<<(BT*DD/4 + 255)/256, 256>>>((const float4*)x, (float4*)xn, BT*DD/4);
    pgemm_nt<1,0,0,0><<<dim3(VV/128, BT/128), 256, PIPE_SMEM>>>(
        xn, DD, wt_lm, DD, lm_b, nullptr, logits, VV, DD);
}

// round 5
// speedup vs baseline: 1.8941x; 1.1380x over previous
#include <cuda_runtime.h>
#include <cuda_fp16.h>
#include <cstdint>
#include <math.h>

// ---------------- problem constants ----------------
#define VV 32000
#define DD 512
#define DI 1024
#define DS 16
#define DC 4
#define DTR 32
#define LL 4
#define HH 2048
#define BB 2
#define TT 1024
#define BT (BB*TT)   // 2048

// ---------------- scratch (static device memory; no allocs allowed) ----------------
__device__ float  g_x   [BT*DD];
__device__ float  g_xz  [BT*2*DI];
__device__ float  g_u   [BT*DI];
__device__ float  g_xdbl[BT*64];
__device__ float  g_dt  [BT*DI];
// fp16 activation buffers (GEMM operands)
__device__ __half g_xn_h[BT*DD];
__device__ __half g_ym_h[BT*DI];
__device__ __half g_hh_h[BT*HH];
// fp16 weight copies
__device__ __half g_wh_in [LL*2*DI*DD];
__device__ __half g_wh_out[LL*DD*DI];
__device__ __half g_wh_f1 [LL*HH*DD];
__device__ __half g_wh_f2 [LL*DD*HH];
__device__ __half g_wh_lm [VV*DD];

// ---------------- helpers ----------------
__device__ __forceinline__ uint32_t smem_u32(const void* p) {
    uint32_t a;
    asm("{ .reg .u64 t; cvta.to.shared.u64 t, %1; cvt.u32.u64 %0, t; }" : "=r"(a) : "l"(p));
    return a;
}

__device__ __forceinline__ void mma_f16(float c[4],
                                        unsigned a0, unsigned a1, unsigned a2, unsigned a3,
                                        unsigned b0, unsigned b1)
{
    asm("mma.sync.aligned.m16n8k16.row.col.f32.f16.f16.f32 "
        "{%0,%1,%2,%3}, {%4,%5,%6,%7}, {%8,%9}, {%0,%1,%2,%3};"
        : "+f"(c[0]), "+f"(c[1]), "+f"(c[2]), "+f"(c[3])
        : "r"(a0), "r"(a1), "r"(a2), "r"(a3), "r"(b0), "r"(b1));
}

// ===== pipelined fp16 mma.sync GEMM (NT): C[m,n] = sum_k A[m,k]*B[n,k] =====
// Block tile 128x128, K-block 16, 6-stage cp.async pipeline, 8 warps (32x64 each).
// Requires M%128==0, N%128==0, K%16==0.
// smem row stride 24 halves (48B) -> word stride 12 == 4 (mod 8): conflict-free frags.
#define HSTRW 12                 // row stride in 32-bit words
#define OPW (128*HSTRW)          // 1536 words per operand per stage
#define STW (2*OPW)              // 3072 words per stage
#define HSTAGES 6
#define HPIPE_SMEM (HSTAGES*STW*4)   // 73728 B

template<int BIAS, int ACT, int RES, int OUT16>
__global__ __launch_bounds__(256) void hgemm_nt(
    const __half* __restrict__ A, int lda,
    const __half* __restrict__ Bw, int ldb,
    const float* __restrict__ bias,
    const float* __restrict__ res,
    void* __restrict__ Cv, int ldc, int K)
{
    extern __shared__ unsigned smw[];
    uint32_t sb = smem_u32(smw);

    int tid  = threadIdx.x;
    int m0   = blockIdx.y * 128;
    int n0   = blockIdx.x * 128;
    int warp = tid >> 5;
    int lane = tid & 31;
    int warpM = warp & 3;         // 4 warps along M (32 rows each)
    int warpN = warp >> 2;        // 2 warps along N (64 cols each)
    int grp  = lane >> 2;         // 0..7
    int tig  = lane & 3;          // 0..3
    int KB = K >> 4;

    // loader: per stage per operand 128 rows x 2 chunks(16B). thread -> (row, q)
    int lrow = tid >> 1, lq = tid & 1;
    const __half* pA = A  + (size_t)(m0 + lrow) * lda + lq * 8;
    const __half* pB = Bw + (size_t)(n0 + lrow) * ldb + lq * 8;
    uint32_t dA = sb + (uint32_t)(lrow * HSTRW + lq * 4) * 4;
    uint32_t dB = dA + OPW * 4;

    auto load_stage = [&](int s, int kb) {
        if (kb < KB) {
            uint32_t o = (uint32_t)s * (STW * 4);
            const __half* sa = pA + (size_t)kb * 16;
            const __half* sbq = pB + (size_t)kb * 16;
            asm volatile("cp.async.cg.shared.global [%0], [%1], 16;" :: "r"(dA + o), "l"(sa));
            asm volatile("cp.async.cg.shared.global [%0], [%1], 16;" :: "r"(dB + o), "l"(sbq));
        }
        asm volatile("cp.async.commit_group;" ::: "memory");
    };

    float acc[2][8][4];
    #pragma unroll
    for (int i = 0; i < 2; i++)
        #pragma unroll
        for (int j = 0; j < 8; j++)
            #pragma unroll
            for (int c = 0; c < 4; c++) acc[i][j][c] = 0.f;

    #pragma unroll
    for (int s = 0; s < HSTAGES - 1; s++) load_stage(s, s);

    for (int kb = 0; kb < KB; kb++) {
        asm volatile("cp.async.wait_group %0;" :: "n"(HSTAGES - 2) : "memory");
        __syncthreads();

        // refill the stage consumed last iteration
        load_stage((kb + HSTAGES - 1) % HSTAGES, kb + HSTAGES - 1);

        const unsigned* st  = smw + (kb % HSTAGES) * STW;
        const unsigned* sa  = st;
        const unsigned* sbp = st + OPW;

        unsigned af[2][4];
        #pragma unroll
        for (int i = 0; i < 2; i++) {
            int rb = warpM * 32 + i * 16;
            af[i][0] = sa[(rb + grp)     * HSTRW + tig];
            af[i][1] = sa[(rb + 8 + grp) * HSTRW + tig];
            af[i][2] = sa[(rb + grp)     * HSTRW + 4 + tig];
            af[i][3] = sa[(rb + 8 + grp) * HSTRW + 4 + tig];
        }
        unsigned bf[8][2];
        #pragma unroll
        for (int j = 0; j < 8; j++) {
            int nb = warpN * 64 + j * 8;
            bf[j][0] = sbp[(nb + grp) * HSTRW + tig];
            bf[j][1] = sbp[(nb + grp) * HSTRW + 4 + tig];
        }
        #pragma unroll
        for (int i = 0; i < 2; i++)
            #pragma unroll
            for (int j = 0; j < 8; j++)
                mma_f16(acc[i][j], af[i][0], af[i][1], af[i][2], af[i][3],
                        bf[j][0], bf[j][1]);
    }

    // epilogue: acc tile m16n8 -> c0,c1 at (grp, 2*tig), c2,c3 at (grp+8, 2*tig)
    #pragma unroll
    for (int i = 0; i < 2; i++) {
        int rbase = m0 + warpM * 32 + i * 16 + grp;
        #pragma unroll
        for (int j = 0; j < 8; j++) {
            int n = n0 + warpN * 64 + j * 8 + tig * 2;
            float bv0 = 0.f, bv1 = 0.f;
            if (BIAS) { bv0 = bias[n]; bv1 = bias[n+1]; }
            #pragma unroll
            for (int h = 0; h < 2; h++) {
                int m = rbase + h * 8;
                float v0 = acc[i][j][2*h+0] + bv0;
                float v1 = acc[i][j][2*h+1] + bv1;
                if (ACT == 1) { v0 = fmaxf(v0, 0.f); v1 = fmaxf(v1, 0.f); }
                if (RES) {
                    float2 r = *(const float2*)(res + (size_t)m * ldc + n);
                    v0 += r.x; v1 += r.y;
                }
                if (OUT16) {
                    __half2* Ch = (__half2*)((__half*)Cv + (size_t)m * ldc + n);
                    *Ch = __floats2half2_rn(v0, v1);
                } else {
                    *(float2*)((float*)Cv + (size_t)m * ldc + n) = make_float2(v0, v1);
                }
            }
        }
    }
}

// ---------------- fp32 -> fp16 conversion ----------------
__global__ void f2h_kernel(const float4* __restrict__ src, __half2* __restrict__ dst, int n4)
{
    int i = blockIdx.x * blockDim.x + threadIdx.x;
    if (i < n4) {
        float4 v = src[i];
        dst[2*i+0] = __floats2half2_rn(v.x, v.y);
        dst[2*i+1] = __floats2half2_rn(v.z, v.w);
    }
}

// ---------------- embedding ----------------
__global__ void embed_kernel(const int* __restrict__ idx,
                             const float* __restrict__ tok_emb,
                             const float* __restrict__ pos_emb,
                             float* __restrict__ x)
{
    int tid = blockIdx.x * blockDim.x + threadIdx.x;
    int d   = tid & (DD-1);
    int tok = tid >> 9;
    int t   = tok & (TT-1);
    int id  = idx[tok];
    x[tid] = tok_emb[(size_t)id*DD + d] + pos_emb[(size_t)t*DD + d];
}

// ---------------- layer norm (half output — feeds tensor GEMMs only) ----------------
__global__ __launch_bounds__(256) void ln_kernel(const float* __restrict__ x,
                                                 const float* __restrict__ gamma,
                                                 const float* __restrict__ beta,
                                                 __half* __restrict__ out)
{
    int tok = blockIdx.x;
    const float* xr = x + (size_t)tok * DD;
    int tid = threadIdx.x;
    float v0 = xr[tid], v1 = xr[tid + 256];

    __shared__ float sm[8];
    __shared__ float mv[2];

    float s = v0 + v1;
    #pragma unroll
    for (int o = 16; o; o >>= 1) s += __shfl_xor_sync(0xffffffffu, s, o);
    int w = tid >> 5, ln = tid & 31;
    if (ln == 0) sm[w] = s;
    __syncthreads();
    if (tid == 0) {
        float tot = 0.f;
        #pragma unroll
        for (int i = 0; i < 8; i++) tot += sm[i];
        mv[0] = tot * (1.f / DD);
    }
    __syncthreads();
    float m  = mv[0];
    float d0 = v0 - m, d1 = v1 - m;
    float sq = d0*d0 + d1*d1;
    #pragma unroll
    for (int o = 16; o; o >>= 1) sq += __shfl_xor_sync(0xffffffffu, sq, o);
    if (ln == 0) sm[w] = sq;
    __syncthreads();
    if (tid == 0) {
        float tot = 0.f;
        #pragma unroll
        for (int i = 0; i < 8; i++) tot += sm[i];
        mv[1] = rsqrtf(tot * (1.f / DD) + 1e-5f);
    }
    __syncthreads();
    float rs = mv[1];
    out[(size_t)tok*DD + tid]       = __float2half_rn(d0 * rs * gamma[tid]       + beta[tid]);
    out[(size_t)tok*DD + tid + 256] = __float2half_rn(d1 * rs * gamma[tid + 256] + beta[tid + 256]);
}

// ---------------- causal depthwise conv (DC=4) + silu ----------------
__global__ void conv_silu_kernel(const float* __restrict__ xz,
                                 const float* __restrict__ w,
                                 const float* __restrict__ cb,
                                 float* __restrict__ u)
{
    int tid = blockIdx.x * blockDim.x + threadIdx.x;
    int i = tid & (DI-1);
    int t = (tid >> 10) & (TT-1);
    int b = tid >> 20;
    float4 wv = *(const float4*)(w + (size_t)i * 4);
    const float* base = xz + ((size_t)(b*TT) + t) * (2*DI) + i;
    float acc = cb[i];
    acc += wv.w * base[0];
    if (t >= 1) acc += wv.z * base[-(2*DI)];
    if (t >= 2) acc += wv.y * base[-2*(2*DI)];
    if (t >= 3) acc += wv.x * base[-3*(2*DI)];
    float sg = 1.f / (1.f + __expf(-acc));
    u[tid] = acc * sg;
}

// ---------------- selective scan (half output — feeds W_out tensor GEMM only) ----------------
__global__ __launch_bounds__(256) void scan_kernel(const float* __restrict__ dt,
                                                   const float* __restrict__ u,
                                                   const float* __restrict__ xdbl,
                                                   const float* __restrict__ xz,
                                                   const float* __restrict__ A_log,
                                                   const float* __restrict__ D_p,
                                                   __half* __restrict__ ym)
{
    int tid = blockIdx.x * blockDim.x + threadIdx.x;
    int s = tid & (DS-1);
    int d = (tid >> 4) & (DI-1);
    int b = tid >> 14;

    float Ads = -expf(A_log[(size_t)d*DS + s]);
    float Dv  = D_p[d];
    float h = 0.f;

    const float* dt_p = dt   + (size_t)b*TT*DI + d;
    const float* u_p  = u    + (size_t)b*TT*DI + d;
    const float* bd   = xdbl + (size_t)b*TT*64 + DTR + s;
    const float* cd   = xdbl + (size_t)b*TT*64 + DTR + DS + s;
    const float* zp   = xz   + (size_t)b*TT*(2*DI) + DI + d;
    __half*      yp   = ym   + (size_t)b*TT*DI + d;

    for (int t = 0; t < TT; t++) {
        float dtv = dt_p[(size_t)t*DI];
        float uv  = u_p [(size_t)t*DI];
        float Bv  = bd  [(size_t)t*64];
        float Cv  = cd  [(size_t)t*64];
        float dA  = __expf(dtv * Ads);
        h = fmaf(dA, h, dtv * uv * Bv);
        float p = h * Cv;
        p += __shfl_xor_sync(0xffffffffu, p, 1);
        p += __shfl_xor_sync(0xffffffffu, p, 2);
        p += __shfl_xor_sync(0xffffffffu, p, 4);
        p += __shfl_xor_sync(0xffffffffu, p, 8);
        if (s == 0) {
            float zv = zp[(size_t)t*(2*DI)];
            float y  = fmaf(uv, Dv, p);
            y = y * (zv / (1.f + __expf(-zv)));
            yp[(size_t)t*DI] = __float2half_rn(y);
        }
    }
}

// ---------------- fp32 SIMT GEMM (NT) for small shapes (W_xp, W_dt) ----------------
#define GBM 128
#define GBN 128
#define GBK 8

__device__ __forceinline__ unsigned long long pack_dup(float a) {
    unsigned long long r;
    asm("mov.b64 %0, {%1, %1};" : "=l"(r) : "f"(a));
    return r;
}

template<int BIAS, int ACT, int RES>
__global__ __launch_bounds__(256) void sgemm_nt(const float* __restrict__ A, int lda,
                                                const float* __restrict__ Bw, int ldb,
                                                const float* __restrict__ bias,
                                                const float* __restrict__ res,
                                                float* __restrict__ C, int ldc,
                                                int M, int N, int K)
{
    __shared__ float As[GBK][GBM];
    __shared__ float Bs[GBK][GBN];

    int tid = threadIdx.x;
    int m0 = blockIdx.y * GBM;
    int n0 = blockIdx.x * GBN;

    int loadRow = tid >> 1;
    int loadK4  = (tid & 1) * 4;

    int tx = tid & 15, ty = tid >> 4;
    int row0 = ty * 8, col0 = tx * 8;

    unsigned long long acc[8][4];
    #pragma unroll
    for (int i = 0; i < 8; i++)
        #pragma unroll
        for (int j = 0; j < 4; j++) acc[i][j] = 0ULL;

    for (int k0 = 0; k0 < K; k0 += GBK) {
        float4 av = *(const float4*)(A + (size_t)(m0 + loadRow) * lda + k0 + loadK4);
        float4 bv = make_float4(0.f, 0.f, 0.f, 0.f);
        int nrow = n0 + loadRow;
        if (nrow < N)
            bv = *(const float4*)(Bw + (size_t)nrow * ldb + k0 + loadK4);

        __syncthreads();
        As[loadK4+0][loadRow] = av.x;
        As[loadK4+1][loadRow] = av.y;
        As[loadK4+2][loadRow] = av.z;
        As[loadK4+3][loadRow] = av.w;
        Bs[loadK4+0][loadRow] = bv.x;
        Bs[loadK4+1][loadRow] = bv.y;
        Bs[loadK4+2][loadRow] = bv.z;
        Bs[loadK4+3][loadRow] = bv.w;
        __syncthreads();

        #pragma unroll
        for (int kk = 0; kk < GBK; kk++) {
            float a[8];
            *(float4*)&a[0] = *(const float4*)&As[kk][row0];
            *(float4*)&a[4] = *(const float4*)&As[kk][row0 + 4];
            unsigned long long b2[4];
            const unsigned long long* bp = (const unsigned long long*)&Bs[kk][col0];
            b2[0] = bp[0]; b2[1] = bp[1]; b2[2] = bp[2]; b2[3] = bp[3];
            #pragma unroll
            for (int i = 0; i < 8; i++) {
                unsigned long long aa = pack_dup(a[i]);
                #pragma unroll
                for (int j = 0; j < 4; j++)
                    asm("fma.rn.f32x2 %0, %1, %2, %0;" : "+l"(acc[i][j]) : "l"(aa), "l"(b2[j]));
            }
        }
    }

    #pragma unroll
    for (int i = 0; i < 8; i++) {
        int m = m0 + row0 + i;
        float vr[8];
        #pragma unroll
        for (int j = 0; j < 4; j++)
            asm("mov.b64 {%0, %1}, %2;" : "=f"(vr[2*j]), "=f"(vr[2*j+1]) : "l"(acc[i][j]));
        #pragma unroll
        for (int j = 0; j < 8; j++) {
            int n = n0 + col0 + j;
            if (n < N) {
                float v = vr[j];
                if (BIAS) v += bias[n];
                if (ACT == 1) v = fmaxf(v, 0.f);
                if (ACT == 2) v = (v > 20.f) ? v : log1pf(expf(v));
                if (RES) v += res[(size_t)m * ldc + n];
                C[(size_t)m * ldc + n] = v;
            }
        }
    }
}

// ---------------- launch ----------------
extern "C" void kernel_launch(void* const* d_in, const int* in_sizes, int n_in,
                              void* d_out, int out_size)
{
    const int*   idx     = (const int*)  d_in[0];
    const float* tok_emb = (const float*)d_in[1];
    const float* pos_emb = (const float*)d_in[2];
    const float* ln1_g   = (const float*)d_in[3];
    const float* ln1_b   = (const float*)d_in[4];
    const float* W_in    = (const float*)d_in[5];
    const float* conv_w  = (const float*)d_in[6];
    const float* conv_b  = (const float*)d_in[7];
    const float* W_xp    = (const float*)d_in[8];
    const float* W_dt    = (const float*)d_in[9];
    const float* b_dt    = (const float*)d_in[10];
    const float* A_log   = (const float*)d_in[11];
    const float* D_p     = (const float*)d_in[12];
    const float* W_out   = (const float*)d_in[13];
    const float* ln2_g   = (const float*)d_in[14];
    const float* ln2_b   = (const float*)d_in[15];
    const float* W_f1    = (const float*)d_in[16];
    const float* b_f1    = (const float*)d_in[17];
    const float* W_f2    = (const float*)d_in[18];
    const float* b_f2    = (const float*)d_in[19];
    const float* lm_w    = (const float*)d_in[20];
    const float* lm_b    = (const float*)d_in[21];
    float* logits = (float*)d_out;

    float *x, *xz, *u, *xdbl, *dt;
    __half *xn_h, *ym_h, *hh_h, *wh_in, *wh_out, *wh_f1, *wh_f2, *wh_lm;
    cudaGetSymbolAddress((void**)&x,     g_x);
    cudaGetSymbolAddress((void**)&xz,    g_xz);
    cudaGetSymbolAddress((void**)&u,     g_u);
    cudaGetSymbolAddress((void**)&xdbl,  g_xdbl);
    cudaGetSymbolAddress((void**)&dt,    g_dt);
    cudaGetSymbolAddress((void**)&xn_h,  g_xn_h);
    cudaGetSymbolAddress((void**)&ym_h,  g_ym_h);
    cudaGetSymbolAddress((void**)&hh_h,  g_hh_h);
    cudaGetSymbolAddress((void**)&wh_in, g_wh_in);
    cudaGetSymbolAddress((void**)&wh_out,g_wh_out);
    cudaGetSymbolAddress((void**)&wh_f1, g_wh_f1);
    cudaGetSymbolAddress((void**)&wh_f2, g_wh_f2);
    cudaGetSymbolAddress((void**)&wh_lm, g_wh_lm);

    cudaFuncSetAttribute(hgemm_nt<0,0,0,0>, cudaFuncAttributeMaxDynamicSharedMemorySize, HPIPE_SMEM);
    cudaFuncSetAttribute(hgemm_nt<0,0,1,0>, cudaFuncAttributeMaxDynamicSharedMemorySize, HPIPE_SMEM);
    cudaFuncSetAttribute(hgemm_nt<1,1,0,1>, cudaFuncAttributeMaxDynamicSharedMemorySize, HPIPE_SMEM);
    cudaFuncSetAttribute(hgemm_nt<1,0,1,0>, cudaFuncAttributeMaxDynamicSharedMemorySize, HPIPE_SMEM);
    cudaFuncSetAttribute(hgemm_nt<1,0,0,0>, cudaFuncAttributeMaxDynamicSharedMemorySize, HPIPE_SMEM);

    // weight conversions to fp16 scratch
    f2h_kernel<<<(LL*2*DI*DD/4 + 255)/256, 256>>>((const float4*)W_in,  (__half2*)wh_in,  LL*2*DI*DD/4);
    f2h_kernel<<<(LL*DD*DI/4   + 255)/256, 256>>>((const float4*)W_out, (__half2*)wh_out, LL*DD*DI/4);
    f2h_kernel<<<(LL*HH*DD/4   + 255)/256, 256>>>((const float4*)W_f1,  (__half2*)wh_f1,  LL*HH*DD/4);
    f2h_kernel<<<(LL*DD*HH/4   + 255)/256, 256>>>((const float4*)W_f2,  (__half2*)wh_f2,  LL*DD*HH/4);
    f2h_kernel<<<(VV*DD/4      + 255)/256, 256>>>((const float4*)lm_w,  (__half2*)wh_lm,  VV*DD/4);

    embed_kernel<<<(BT*DD)/256, 256>>>(idx, tok_emb, pos_emb, x);

    for (int l = 0; l < LL; l++) {
        // ln1 -> fp16
        ln_kernel<<<BT, 256>>>(x, ln1_g + l*DD, ln1_b + l*DD, xn_h);
        // xz = xn @ W_in^T   (2048 x 2048 x 512)
        hgemm_nt<0,0,0,0><<<dim3(2*DI/128, BT/128), 256, HPIPE_SMEM>>>(
            xn_h, DD, wh_in + (size_t)l*2*DI*DD, DD, nullptr, nullptr, xz, 2*DI, DD);
        // depthwise conv + silu -> u (fp32)
        conv_silu_kernel<<<(BT*DI)/256, 256>>>(xz, conv_w + (size_t)l*DI*DC, conv_b + l*DI, u);
        // x_dbl = u @ W_xp^T   (2048 x 64 x 1024) — SIMT fp32 (exact)
        sgemm_nt<0,0,0><<<dim3(1, BT/GBM), 256>>>(
            u, DI, W_xp + (size_t)l*64*DI, DI, nullptr, nullptr, xdbl, 64, BT, 64, DI);
        // dt = softplus(x_dbl[:, :32] @ W_dt^T + b_dt) — SIMT fp32 (exact)
        sgemm_nt<1,2,0><<<dim3(DI/GBN, BT/GBM), 256>>>(
            xdbl, 64, W_dt + (size_t)l*DI*DTR, DTR, b_dt + l*DI, nullptr, dt, DI, BT, DI, DTR);
        // selective scan -> ym (fp16 output)
        scan_kernel<<<(BB*DI*DS)/256, 256>>>(dt, u, xdbl, xz,
                                             A_log + (size_t)l*DI*DS, D_p + l*DI, ym_h);
        // x += ym @ W_out^T   (2048 x 512 x 1024)
        hgemm_nt<0,0,1,0><<<dim3(DD/128, BT/128), 256, HPIPE_SMEM>>>(
            ym_h, DI, wh_out + (size_t)l*DD*DI, DI, nullptr, x, x, DD, DI);
        // ln2 -> fp16
        ln_kernel<<<BT, 256>>>(x, ln2_g + l*DD, ln2_b + l*DD, xn_h);
        // hh = relu(xn @ W_f1^T + b_f1)  (2048 x 2048 x 512) -> fp16
        hgemm_nt<1,1,0,1><<<dim3(HH/128, BT/128), 256, HPIPE_SMEM>>>(
            xn_h, DD, wh_f1 + (size_t)l*HH*DD, DD, b_f1 + l*HH, nullptr, hh_h, HH, DD);
        // x += hh @ W_f2^T + b_f2   (2048 x 512 x 2048)
        hgemm_nt<1,0,1,0><<<dim3(DD/128, BT/128), 256, HPIPE_SMEM>>>(
            hh_h, HH, wh_f2 + (size_t)l*DD*HH, HH, b_f2 + l*DD, x, x, DD, HH);
    }

    // lm input -> fp16, then logits = x @ lm_w^T + lm_b  (2048 x 32000 x 512)
    f2h_kernel<<<(BT*DD/4 + 255)/256, 256>>>((const float4*)x, (__half2*)xn_h, BT*DD/4);
    hgemm_nt<1,0,0,0><<<dim3(VV/128, BT/128), 256, HPIPE_SMEM>>>(
        xn_h, DD, wh_lm, DD, lm_b, nullptr, logits, VV, DD);
}

// round 6
// speedup vs baseline: 1.9154x; 1.0112x over previous
#include <cuda_runtime.h>
#include <cuda_fp16.h>
#include <cstdint>
#include <math.h>

// ---------------- problem constants ----------------
#define VV 32000
#define DD 512
#define DI 1024
#define DS 16
#define DC 4
#define DTR 32
#define LL 4
#define HH 2048
#define BB 2
#define TT 1024
#define BT (BB*TT)   // 2048

// ---------------- scratch (static device memory; no allocs allowed) ----------------
__device__ float  g_x   [BT*DD];
__device__ float  g_xz  [BT*2*DI];
__device__ float  g_u   [BT*DI];
__device__ float  g_xdbl[BT*64];
__device__ float  g_dt  [BT*DI];
// fp16 activation buffers (GEMM operands)
__device__ __half g_xn_h[BT*DD];
__device__ __half g_ym_h[BT*DI];
__device__ __half g_hh_h[BT*HH];
// fp16 weight copies
__device__ __half g_wh_in [LL*2*DI*DD];
__device__ __half g_wh_out[LL*DD*DI];
__device__ __half g_wh_f1 [LL*HH*DD];
__device__ __half g_wh_f2 [LL*DD*HH];
__device__ __half g_wh_lm [VV*DD];

// ---------------- helpers ----------------
__device__ __forceinline__ uint32_t smem_u32(const void* p) {
    uint32_t a;
    asm("{ .reg .u64 t; cvta.to.shared.u64 t, %1; cvt.u32.u64 %0, t; }" : "=r"(a) : "l"(p));
    return a;
}

__device__ __forceinline__ void mma_f16(float c[4],
                                        unsigned a0, unsigned a1, unsigned a2, unsigned a3,
                                        unsigned b0, unsigned b1)
{
    asm("mma.sync.aligned.m16n8k16.row.col.f32.f16.f16.f32 "
        "{%0,%1,%2,%3}, {%4,%5,%6,%7}, {%8,%9}, {%0,%1,%2,%3};"
        : "+f"(c[0]), "+f"(c[1]), "+f"(c[2]), "+f"(c[3])
        : "r"(a0), "r"(a1), "r"(a2), "r"(a3), "r"(b0), "r"(b1));
}

// ===== pipelined fp16 mma.sync GEMM (NT): C[m,n] = sum_k A[m,k]*B[n,k] =====
// Block tile 128x128, K-block 16, 6-stage cp.async pipeline, 8 warps (32x64 each).
// Requires M%128==0, N%128==0, K%16==0.
// smem row stride 24 halves (48B) -> word stride 12 == 4 (mod 8): conflict-free frags.
#define HSTRW 12                 // row stride in 32-bit words
#define OPW (128*HSTRW)          // 1536 words per operand per stage
#define STW (2*OPW)              // 3072 words per stage
#define HSTAGES 6
#define HPIPE_SMEM (HSTAGES*STW*4)   // 73728 B

template<int BIAS, int ACT, int RES, int OUT16>
__global__ __launch_bounds__(256) void hgemm_nt(
    const __half* __restrict__ A, int lda,
    const __half* __restrict__ Bw, int ldb,
    const float* __restrict__ bias,
    const float* __restrict__ res,
    void* __restrict__ Cv, int ldc, int K)
{
    extern __shared__ unsigned smw[];
    uint32_t sb = smem_u32(smw);

    int tid  = threadIdx.x;
    int m0   = blockIdx.y * 128;
    int n0   = blockIdx.x * 128;
    int warp = tid >> 5;
    int lane = tid & 31;
    int warpM = warp & 3;         // 4 warps along M (32 rows each)
    int warpN = warp >> 2;        // 2 warps along N (64 cols each)
    int grp  = lane >> 2;         // 0..7
    int tig  = lane & 3;          // 0..3
    int KB = K >> 4;

    // loader: per stage per operand 128 rows x 2 chunks(16B). thread -> (row, q)
    int lrow = tid >> 1, lq = tid & 1;
    const __half* pA = A  + (size_t)(m0 + lrow) * lda + lq * 8;
    const __half* pB = Bw + (size_t)(n0 + lrow) * ldb + lq * 8;
    uint32_t dA = sb + (uint32_t)(lrow * HSTRW + lq * 4) * 4;
    uint32_t dB = dA + OPW * 4;

    auto load_stage = [&](int s, int kb) {
        if (kb < KB) {
            uint32_t o = (uint32_t)s * (STW * 4);
            const __half* sa = pA + (size_t)kb * 16;
            const __half* sbq = pB + (size_t)kb * 16;
            asm volatile("cp.async.cg.shared.global [%0], [%1], 16;" :: "r"(dA + o), "l"(sa));
            asm volatile("cp.async.cg.shared.global [%0], [%1], 16;" :: "r"(dB + o), "l"(sbq));
        }
        asm volatile("cp.async.commit_group;" ::: "memory");
    };

    float acc[2][8][4];
    #pragma unroll
    for (int i = 0; i < 2; i++)
        #pragma unroll
        for (int j = 0; j < 8; j++)
            #pragma unroll
            for (int c = 0; c < 4; c++) acc[i][j][c] = 0.f;

    #pragma unroll
    for (int s = 0; s < HSTAGES - 1; s++) load_stage(s, s);

    for (int kb = 0; kb < KB; kb++) {
        asm volatile("cp.async.wait_group %0;" :: "n"(HSTAGES - 2) : "memory");
        __syncthreads();

        // refill the stage consumed last iteration
        load_stage((kb + HSTAGES - 1) % HSTAGES, kb + HSTAGES - 1);

        const unsigned* st  = smw + (kb % HSTAGES) * STW;
        const unsigned* sa  = st;
        const unsigned* sbp = st + OPW;

        unsigned af[2][4];
        #pragma unroll
        for (int i = 0; i < 2; i++) {
            int rb = warpM * 32 + i * 16;
            af[i][0] = sa[(rb + grp)     * HSTRW + tig];
            af[i][1] = sa[(rb + 8 + grp) * HSTRW + tig];
            af[i][2] = sa[(rb + grp)     * HSTRW + 4 + tig];
            af[i][3] = sa[(rb + 8 + grp) * HSTRW + 4 + tig];
        }
        unsigned bf[8][2];
        #pragma unroll
        for (int j = 0; j < 8; j++) {
            int nb = warpN * 64 + j * 8;
            bf[j][0] = sbp[(nb + grp) * HSTRW + tig];
            bf[j][1] = sbp[(nb + grp) * HSTRW + 4 + tig];
        }
        #pragma unroll
        for (int i = 0; i < 2; i++)
            #pragma unroll
            for (int j = 0; j < 8; j++)
                mma_f16(acc[i][j], af[i][0], af[i][1], af[i][2], af[i][3],
                        bf[j][0], bf[j][1]);
    }

    // epilogue: acc tile m16n8 -> c0,c1 at (grp, 2*tig), c2,c3 at (grp+8, 2*tig)
    #pragma unroll
    for (int i = 0; i < 2; i++) {
        int rbase = m0 + warpM * 32 + i * 16 + grp;
        #pragma unroll
        for (int j = 0; j < 8; j++) {
            int n = n0 + warpN * 64 + j * 8 + tig * 2;
            float bv0 = 0.f, bv1 = 0.f;
            if (BIAS) { bv0 = bias[n]; bv1 = bias[n+1]; }
            #pragma unroll
            for (int h = 0; h < 2; h++) {
                int m = rbase + h * 8;
                float v0 = acc[i][j][2*h+0] + bv0;
                float v1 = acc[i][j][2*h+1] + bv1;
                if (ACT == 1) { v0 = fmaxf(v0, 0.f); v1 = fmaxf(v1, 0.f); }
                if (RES) {
                    float2 r = *(const float2*)(res + (size_t)m * ldc + n);
                    v0 += r.x; v1 += r.y;
                }
                if (OUT16) {
                    __half2* Ch = (__half2*)((__half*)Cv + (size_t)m * ldc + n);
                    *Ch = __floats2half2_rn(v0, v1);
                } else {
                    *(float2*)((float*)Cv + (size_t)m * ldc + n) = make_float2(v0, v1);
                }
            }
        }
    }
}

// ---------------- fp32 -> fp16 conversion ----------------
__global__ void f2h_kernel(const float4* __restrict__ src, __half2* __restrict__ dst, int n4)
{
    int i = blockIdx.x * blockDim.x + threadIdx.x;
    if (i < n4) {
        float4 v = src[i];
        dst[2*i+0] = __floats2half2_rn(v.x, v.y);
        dst[2*i+1] = __floats2half2_rn(v.z, v.w);
    }
}

// ---------------- embedding ----------------
__global__ void embed_kernel(const int* __restrict__ idx,
                             const float* __restrict__ tok_emb,
                             const float* __restrict__ pos_emb,
                             float* __restrict__ x)
{
    int tid = blockIdx.x * blockDim.x + threadIdx.x;
    int d   = tid & (DD-1);
    int tok = tid >> 9;
    int t   = tok & (TT-1);
    int id  = idx[tok];
    x[tid] = tok_emb[(size_t)id*DD + d] + pos_emb[(size_t)t*DD + d];
}

// ---------------- layer norm (half output — feeds tensor GEMMs only) ----------------
__global__ __launch_bounds__(256) void ln_kernel(const float* __restrict__ x,
                                                 const float* __restrict__ gamma,
                                                 const float* __restrict__ beta,
                                                 __half* __restrict__ out)
{
    int tok = blockIdx.x;
    const float* xr = x + (size_t)tok * DD;
    int tid = threadIdx.x;
    float v0 = xr[tid], v1 = xr[tid + 256];

    __shared__ float sm[8];
    __shared__ float mv[2];

    float s = v0 + v1;
    #pragma unroll
    for (int o = 16; o; o >>= 1) s += __shfl_xor_sync(0xffffffffu, s, o);
    int w = tid >> 5, ln = tid & 31;
    if (ln == 0) sm[w] = s;
    __syncthreads();
    if (tid == 0) {
        float tot = 0.f;
        #pragma unroll
        for (int i = 0; i < 8; i++) tot += sm[i];
        mv[0] = tot * (1.f / DD);
    }
    __syncthreads();
    float m  = mv[0];
    float d0 = v0 - m, d1 = v1 - m;
    float sq = d0*d0 + d1*d1;
    #pragma unroll
    for (int o = 16; o; o >>= 1) sq += __shfl_xor_sync(0xffffffffu, sq, o);
    if (ln == 0) sm[w] = sq;
    __syncthreads();
    if (tid == 0) {
        float tot = 0.f;
        #pragma unroll
        for (int i = 0; i < 8; i++) tot += sm[i];
        mv[1] = rsqrtf(tot * (1.f / DD) + 1e-5f);
    }
    __syncthreads();
    float rs = mv[1];
    out[(size_t)tok*DD + tid]       = __float2half_rn(d0 * rs * gamma[tid]       + beta[tid]);
    out[(size_t)tok*DD + tid + 256] = __float2half_rn(d1 * rs * gamma[tid + 256] + beta[tid + 256]);
}

// ---------------- causal depthwise conv (DC=4) + silu ----------------
__global__ void conv_silu_kernel(const float* __restrict__ xz,
                                 const float* __restrict__ w,
                                 const float* __restrict__ cb,
                                 float* __restrict__ u)
{
    int tid = blockIdx.x * blockDim.x + threadIdx.x;
    int i = tid & (DI-1);
    int t = (tid >> 10) & (TT-1);
    int b = tid >> 20;
    float4 wv = *(const float4*)(w + (size_t)i * 4);
    const float* base = xz + ((size_t)(b*TT) + t) * (2*DI) + i;
    float acc = cb[i];
    acc += wv.w * base[0];
    if (t >= 1) acc += wv.z * base[-(2*DI)];
    if (t >= 2) acc += wv.y * base[-2*(2*DI)];
    if (t >= 3) acc += wv.x * base[-3*(2*DI)];
    float sg = 1.f / (1.f + __expf(-acc));
    u[tid] = acc * sg;
}

// ---------------- selective scan (half output — feeds W_out tensor GEMM only) ----------------
__global__ __launch_bounds__(256) void scan_kernel(const float* __restrict__ dt,
                                                   const float* __restrict__ u,
                                                   const float* __restrict__ xdbl,
                                                   const float* __restrict__ xz,
                                                   const float* __restrict__ A_log,
                                                   const float* __restrict__ D_p,
                                                   __half* __restrict__ ym)
{
    int tid = blockIdx.x * blockDim.x + threadIdx.x;
    int s = tid & (DS-1);
    int d = (tid >> 4) & (DI-1);
    int b = tid >> 14;

    float Ads = -expf(A_log[(size_t)d*DS + s]);
    float Dv  = D_p[d];
    float h = 0.f;

    const float* dt_p = dt   + (size_t)b*TT*DI + d;
    const float* u_p  = u    + (size_t)b*TT*DI + d;
    const float* bd   = xdbl + (size_t)b*TT*64 + DTR + s;
    const float* cd   = xdbl + (size_t)b*TT*64 + DTR + DS + s;
    const float* zp   = xz   + (size_t)b*TT*(2*DI) + DI + d;
    __half*      yp   = ym   + (size_t)b*TT*DI + d;

    for (int t = 0; t < TT; t++) {
        float dtv = dt_p[(size_t)t*DI];
        float uv  = u_p [(size_t)t*DI];
        float Bv  = bd  [(size_t)t*64];
        float Cv  = cd  [(size_t)t*64];
        float dA  = __expf(dtv * Ads);
        h = fmaf(dA, h, dtv * uv * Bv);
        float p = h * Cv;
        p += __shfl_xor_sync(0xffffffffu, p, 1);
        p += __shfl_xor_sync(0xffffffffu, p, 2);
        p += __shfl_xor_sync(0xffffffffu, p, 4);
        p += __shfl_xor_sync(0xffffffffu, p, 8);
        if (s == 0) {
            float zv = zp[(size_t)t*(2*DI)];
            float y  = fmaf(uv, Dv, p);
            y = y * (zv / (1.f + __expf(-zv)));
            yp[(size_t)t*DI] = __float2half_rn(y);
        }
    }
}

// ---------------- fp32 SIMT GEMM (NT) for small shapes (W_xp, W_dt) ----------------
#define GBM 128
#define GBN 128
#define GBK 8

__device__ __forceinline__ unsigned long long pack_dup(float a) {
    unsigned long long r;
    asm("mov.b64 %0, {%1, %1};" : "=l"(r) : "f"(a));
    return r;
}

template<int BIAS, int ACT, int RES>
__global__ __launch_bounds__(256) void sgemm_nt(const float* __restrict__ A, int lda,
                                                const float* __restrict__ Bw, int ldb,
                                                const float* __restrict__ bias,
                                                const float* __restrict__ res,
                                                float* __restrict__ C, int ldc,
                                                int M, int N, int K)
{
    __shared__ float As[GBK][GBM];
    __shared__ float Bs[GBK][GBN];

    int tid = threadIdx.x;
    int m0 = blockIdx.y * GBM;
    int n0 = blockIdx.x * GBN;

    int loadRow = tid >> 1;
    int loadK4  = (tid & 1) * 4;

    int tx = tid & 15, ty = tid >> 4;
    int row0 = ty * 8, col0 = tx * 8;

    unsigned long long acc[8][4];
    #pragma unroll
    for (int i = 0; i < 8; i++)
        #pragma unroll
        for (int j = 0; j < 4; j++) acc[i][j] = 0ULL;

    for (int k0 = 0; k0 < K; k0 += GBK) {
        float4 av = *(const float4*)(A + (size_t)(m0 + loadRow) * lda + k0 + loadK4);
        float4 bv = make_float4(0.f, 0.f, 0.f, 0.f);
        int nrow = n0 + loadRow;
        if (nrow < N)
            bv = *(const float4*)(Bw + (size_t)nrow * ldb + k0 + loadK4);

        __syncthreads();
        As[loadK4+0][loadRow] = av.x;
        As[loadK4+1][loadRow] = av.y;
        As[loadK4+2][loadRow] = av.z;
        As[loadK4+3][loadRow] = av.w;
        Bs[loadK4+0][loadRow] = bv.x;
        Bs[loadK4+1][loadRow] = bv.y;
        Bs[loadK4+2][loadRow] = bv.z;
        Bs[loadK4+3][loadRow] = bv.w;
        __syncthreads();

        #pragma unroll
        for (int kk = 0; kk < GBK; kk++) {
            float a[8];
            *(float4*)&a[0] = *(const float4*)&As[kk][row0];
            *(float4*)&a[4] = *(const float4*)&As[kk][row0 + 4];
            unsigned long long b2[4];
            const unsigned long long* bp = (const unsigned long long*)&Bs[kk][col0];
            b2[0] = bp[0]; b2[1] = bp[1]; b2[2] = bp[2]; b2[3] = bp[3];
            #pragma unroll
            for (int i = 0; i < 8; i++) {
                unsigned long long aa = pack_dup(a[i]);
                #pragma unroll
                for (int j = 0; j < 4; j++)
                    asm("fma.rn.f32x2 %0, %1, %2, %0;" : "+l"(acc[i][j]) : "l"(aa), "l"(b2[j]));
            }
        }
    }

    #pragma unroll
    for (int i = 0; i < 8; i++) {
        int m = m0 + row0 + i;
        float vr[8];
        #pragma unroll
        for (int j = 0; j < 4; j++)
            asm("mov.b64 {%0, %1}, %2;" : "=f"(vr[2*j]), "=f"(vr[2*j+1]) : "l"(acc[i][j]));
        #pragma unroll
        for (int j = 0; j < 8; j++) {
            int n = n0 + col0 + j;
            if (n < N) {
                float v = vr[j];
                if (BIAS) v += bias[n];
                if (ACT == 1) v = fmaxf(v, 0.f);
                if (ACT == 2) v = (v > 20.f) ? v : log1pf(expf(v));
                if (RES) v += res[(size_t)m * ldc + n];
                C[(size_t)m * ldc + n] = v;
            }
        }
    }
}

// ---------------- launch ----------------
extern "C" void kernel_launch(void* const* d_in, const int* in_sizes, int n_in,
                              void* d_out, int out_size)
{
    const int*   idx     = (const int*)  d_in[0];
    const float* tok_emb = (const float*)d_in[1];
    const float* pos_emb = (const float*)d_in[2];
    const float* ln1_g   = (const float*)d_in[3];
    const float* ln1_b   = (const float*)d_in[4];
    const float* W_in    = (const float*)d_in[5];
    const float* conv_w  = (const float*)d_in[6];
    const float* conv_b  = (const float*)d_in[7];
    const float* W_xp    = (const float*)d_in[8];
    const float* W_dt    = (const float*)d_in[9];
    const float* b_dt    = (const float*)d_in[10];
    const float* A_log   = (const float*)d_in[11];
    const float* D_p     = (const float*)d_in[12];
    const float* W_out   = (const float*)d_in[13];
    const float* ln2_g   = (const float*)d_in[14];
    const float* ln2_b   = (const float*)d_in[15];
    const float* W_f1    = (const float*)d_in[16];
    const float* b_f1    = (const float*)d_in[17];
    const float* W_f2    = (const float*)d_in[18];
    const float* b_f2    = (const float*)d_in[19];
    const float* lm_w    = (const float*)d_in[20];
    const float* lm_b    = (const float*)d_in[21];
    float* logits = (float*)d_out;

    float *x, *xz, *u, *xdbl, *dt;
    __half *xn_h, *ym_h, *hh_h, *wh_in, *wh_out, *wh_f1, *wh_f2, *wh_lm;
    cudaGetSymbolAddress((void**)&x,     g_x);
    cudaGetSymbolAddress((void**)&xz,    g_xz);
    cudaGetSymbolAddress((void**)&u,     g_u);
    cudaGetSymbolAddress((void**)&xdbl,  g_xdbl);
    cudaGetSymbolAddress((void**)&dt,    g_dt);
    cudaGetSymbolAddress((void**)&xn_h,  g_xn_h);
    cudaGetSymbolAddress((void**)&ym_h,  g_ym_h);
    cudaGetSymbolAddress((void**)&hh_h,  g_hh_h);
    cudaGetSymbolAddress((void**)&wh_in, g_wh_in);
    cudaGetSymbolAddress((void**)&wh_out,g_wh_out);
    cudaGetSymbolAddress((void**)&wh_f1, g_wh_f1);
    cudaGetSymbolAddress((void**)&wh_f2, g_wh_f2);
    cudaGetSymbolAddress((void**)&wh_lm, g_wh_lm);

    cudaFuncSetAttribute(hgemm_nt<0,0,0,0>, cudaFuncAttributeMaxDynamicSharedMemorySize, HPIPE_SMEM);
    cudaFuncSetAttribute(hgemm_nt<0,0,1,0>, cudaFuncAttributeMaxDynamicSharedMemorySize, HPIPE_SMEM);
    cudaFuncSetAttribute(hgemm_nt<1,1,0,1>, cudaFuncAttributeMaxDynamicSharedMemorySize, HPIPE_SMEM);
    cudaFuncSetAttribute(hgemm_nt<1,0,1,0>, cudaFuncAttributeMaxDynamicSharedMemorySize, HPIPE_SMEM);
    cudaFuncSetAttribute(hgemm_nt<1,0,0,0>, cudaFuncAttributeMaxDynamicSharedMemorySize, HPIPE_SMEM);

    // weight conversions to fp16 scratch
    f2h_kernel<<<(LL*2*DI*DD/4 + 255)/256, 256>>>((const float4*)W_in,  (__half2*)wh_in,  LL*2*DI*DD/4);
    f2h_kernel<<<(LL*DD*DI/4   + 255)/256, 256>>>((const float4*)W_out, (__half2*)wh_out, LL*DD*DI/4);
    f2h_kernel<<<(LL*HH*DD/4   + 255)/256, 256>>>((const float4*)W_f1,  (__half2*)wh_f1,  LL*HH*DD/4);
    f2h_kernel<<<(LL*DD*HH/4   + 255)/256, 256>>>((const float4*)W_f2,  (__half2*)wh_f2,  LL*DD*HH/4);
    f2h_kernel<<<(VV*DD/4      + 255)/256, 256>>>((const float4*)lm_w,  (__half2*)wh_lm,  VV*DD/4);

    embed_kernel<<<(BT*DD)/256, 256>>>(idx, tok_emb, pos_emb, x);

    for (int l = 0; l < LL; l++) {
        // ln1 -> fp16
        ln_kernel<<<BT, 256>>>(x, ln1_g + l*DD, ln1_b + l*DD, xn_h);
        // xz = xn @ W_in^T   (2048 x 2048 x 512)
        hgemm_nt<0,0,0,0><<<dim3(2*DI/128, BT/128), 256, HPIPE_SMEM>>>(
            xn_h, DD, wh_in + (size_t)l*2*DI*DD, DD, nullptr, nullptr, xz, 2*DI, DD);
        // depthwise conv + silu -> u (fp32)
        conv_silu_kernel<<<(BT*DI)/256, 256>>>(xz, conv_w + (size_t)l*DI*DC, conv_b + l*DI, u);
        // x_dbl = u @ W_xp^T   (2048 x 64 x 1024) — SIMT fp32 (exact)
        sgemm_nt<0,0,0><<<dim3(1, BT/GBM), 256>>>(
            u, DI, W_xp + (size_t)l*64*DI, DI, nullptr, nullptr, xdbl, 64, BT, 64, DI);
        // dt = softplus(x_dbl[:, :32] @ W_dt^T + b_dt) — SIMT fp32 (exact)
        sgemm_nt<1,2,0><<<dim3(DI/GBN, BT/GBM), 256>>>(
            xdbl, 64, W_dt + (size_t)l*DI*DTR, DTR, b_dt + l*DI, nullptr, dt, DI, BT, DI, DTR);
        // selective scan -> ym (fp16 output)
        scan_kernel<<<(BB*DI*DS)/256, 256>>>(dt, u, xdbl, xz,
                                             A_log + (size_t)l*DI*DS, D_p + l*DI, ym_h);
        // x += ym @ W_out^T   (2048 x 512 x 1024)
        hgemm_nt<0,0,1,0><<<dim3(DD/128, BT/128), 256, HPIPE_SMEM>>>(
            ym_h, DI, wh_out + (size_t)l*DD*DI, DI, nullptr, x, x, DD, DI);
        // ln2 -> fp16
        ln_kernel<<<BT, 256>>>(x, ln2_g + l*DD, ln2_b + l*DD, xn_h);
        // hh = relu(xn @ W_f1^T + b_f1)  (2048 x 2048 x 512) -> fp16
        hgemm_nt<1,1,0,1><<<dim3(HH/128, BT/128), 256, HPIPE_SMEM>>>(
            xn_h, DD, wh_f1 + (size_t)l*HH*DD, DD, b_f1 + l*HH, nullptr, hh_h, HH, DD);
        // x += hh @ W_f2^T + b_f2   (2048 x 512 x 2048)
        hgemm_nt<1,0,1,0><<<dim3(DD/128, BT/128), 256, HPIPE_SMEM>>>(
            hh_h, HH, wh_f2 + (size_t)l*DD*HH, HH, b_f2 + l*DD, x, x, DD, HH);
    }

    // lm input -> fp16, then logits = x @ lm_w^T + lm_b  (2048 x 32000 x 512)
    f2h_kernel<<<(BT*DD/4 + 255)/256, 256>>>((const float4*)x, (__half2*)xn_h, BT*DD/4);
    hgemm_nt<1,0,0,0><<<dim3(VV/128, BT/128), 256, HPIPE_SMEM>>>(
        xn_h, DD, wh_lm, DD, lm_b, nullptr, logits, VV, DD);
}